// round 11
// baseline (speedup 1.0000x reference)
#include <cuda_runtime.h>
#include <cuda_bf16.h>
#include <cstdint>

#define FULL 0xFFFFFFFFu

constexpr int B   = 2048;
constexpr int NA  = 60;
constexpr int DG  = 6;
constexpr int AF  = 37;
constexpr int BF  = 6;
constexpr int HID = 128;
constexpr int NC  = 12;
constexpr int BN  = B * NA;
constexpr int NCHK = BN / 256;      // 480 bucket chunks
constexpr int MAXT = 1926;          // max total conv tiles

// ---- scratch (allocation-free) ----
__device__ float    g_x1[BN * HID];
__device__ float    g_x2[BN * HID];
__device__ int      g_bidx[7 * BN];
__device__ int      g_bcnt[8];
__device__ int      g_tbase[8];
__device__ int      g_ccnt[7 * NCHK];   // per-(deg,chunk) counts
__device__ int      g_boff[7 * NCHK];   // exclusive per-(deg,chunk) offsets
__device__ uint32_t g_rank[BN];         // (deg<<16)|rank-in-chunk
// B-fragment-packed weights: entry (deg,c,w,j,lane) -> uint4{hi@kp0,hi@kp1,lo@kp0,lo@kp1}
__device__ uint4    g_WB1[6 * 3 * 512];
__device__ uint4    g_WB2[6 * 9 * 512];
__device__ uint4    g_WBo[9 * 512];

__device__ __forceinline__ float htanh(float x) {
    float y; asm("tanh.approx.f32 %0, %1;" : "=f"(y) : "f"(x)); return y;
}
__device__ __forceinline__ uint16_t bf16b(float x) {
    return __bfloat16_as_ushort(__float2bfloat16(x));
}
__device__ __forceinline__ uint32_t smem_u32(const void* p) {
    uint32_t a;
    asm("{ .reg .u64 t; cvta.to.shared.u64 t, %1; cvt.u32.u64 %0, t; }" : "=r"(a) : "l"(p));
    return a;
}
__device__ __forceinline__ void mma16816(float* d, const uint32_t* a, const uint32_t* b) {
    asm volatile("mma.sync.aligned.m16n8k16.row.col.f32.bf16.bf16.f32 "
                 "{%0,%1,%2,%3}, {%4,%5,%6,%7}, {%8,%9}, {%0,%1,%2,%3};"
                 : "+f"(d[0]), "+f"(d[1]), "+f"(d[2]), "+f"(d[3])
                 : "r"(a[0]), "r"(a[1]), "r"(a[2]), "r"(a[3]), "r"(b[0]), "r"(b[1]));
}
#define LDSM_X4(r, a) \
    asm volatile("ldmatrix.sync.aligned.m8n8.x4.shared.b16 {%0,%1,%2,%3}, [%4];" \
                 : "=r"((r)[0]), "=r"((r)[1]), "=r"((r)[2]), "=r"((r)[3]) : "r"(a))

// ==================== deterministic id-stable bucketing ====================
__global__ __launch_bounds__(256)
void bucketA_kernel(const int* __restrict__ edges) {
    __shared__ int sw[8][7], sp[8][7];
    int tid = threadIdx.x, w = tid >> 5, lane = tid & 31;
    int a = blockIdx.x * 256 + tid;
    int deg = 0;
    #pragma unroll
    for (int d = 0; d < DG; d++) deg += (edges[a * DG + d] >= 0);

    unsigned lt = (1u << lane) - 1u;
    int myrw = 0;
    #pragma unroll
    for (int dd = 0; dd < 7; dd++) {
        unsigned m = __ballot_sync(FULL, deg == dd);
        if (deg == dd) myrw = __popc(m & lt);
        if (lane == 0) sw[w][dd] = __popc(m);
    }
    __syncthreads();
    if (tid < 7) {
        int s = 0;
        #pragma unroll
        for (int w2 = 0; w2 < 8; w2++) { sp[w2][tid] = s; s += sw[w2][tid]; }
        g_ccnt[tid * NCHK + blockIdx.x] = s;
    }
    __syncthreads();
    g_rank[a] = ((uint32_t)deg << 16) | (uint32_t)(sp[w][deg] + myrw);
}

__global__ void bucketB_kernel() {    // 1 block, 224 threads = 7 warps (one per degree)
    int tid = threadIdx.x, d = tid >> 5, lane = tid & 31;
    if (d < 7) {
        int carry = 0;
        for (int base = 0; base < NCHK; base += 32) {     // 480 = 15*32 exact
            int i = base + lane;
            int v = g_ccnt[d * NCHK + i];
            int ov = v;
            #pragma unroll
            for (int o = 1; o < 32; o <<= 1) {
                int t = __shfl_up_sync(FULL, v, o);
                if (lane >= o) v += t;
            }
            g_boff[d * NCHK + i] = carry + v - ov;
            carry += __shfl_sync(FULL, v, 31);
        }
        if (lane == 0) g_bcnt[d] = carry;
    }
    __syncthreads();
    if (tid == 0) {
        int s = 0;
        #pragma unroll
        for (int d2 = 0; d2 < 7; d2++) { g_tbase[d2] = s; s += (g_bcnt[d2] + 63) >> 6; }
        g_tbase[7] = s;
    }
}

__global__ __launch_bounds__(256)
void bucketC_kernel() {
    int a = blockIdx.x * 256 + threadIdx.x;
    uint32_t word = g_rank[a];
    int d = word >> 16, r = word & 0xFFFF;
    g_bidx[d * BN + g_boff[d * NCHK + blockIdx.x] + r] = a;
}

// ==================== weight repack (B-fragment layout) ====================
__device__ __forceinline__ void wsplit4(const float* __restrict__ W, uint4* dst,
                                        int IN, int NCH, int sub) {
    int lane = sub & 31;
    int j    = (sub >> 5) & 1;
    int w    = (sub >> 6) & 7;
    int rest = sub >> 9;
    int c    = rest % NCH;
    int deg  = rest / NCH;
    int tq = lane >> 2, tr = lane & 3;
    int ch  = w * 16 + j * 8 + tq;
    int kp0 = c * 8 + tr, kp1 = kp0 + 4;

    uint32_t ww[4];
    #pragma unroll
    for (int q = 0; q < 2; q++) {
        int kp = q ? kp1 : kp0;
        int k0 = 2 * kp, k1 = 2 * kp + 1;
        float w0 = (k0 < IN) ? W[(deg * IN + k0) * HID + ch] : 0.f;
        float w1 = (k1 < IN) ? W[(deg * IN + k1) * HID + ch] : 0.f;
        __nv_bfloat16 h0 = __float2bfloat16(w0), h1 = __float2bfloat16(w1);
        ww[q]     = (uint32_t)__bfloat16_as_ushort(h0) |
                    ((uint32_t)__bfloat16_as_ushort(h1) << 16);
        ww[2 + q] = (uint32_t)bf16b(w0 - __bfloat162float(h0)) |
                    ((uint32_t)bf16b(w1 - __bfloat162float(h1)) << 16);
    }
    dst[sub] = make_uint4(ww[0], ww[1], ww[2], ww[3]);
}

__global__ __launch_bounds__(256)
void wprep_all_kernel(const float* __restrict__ W1, const float* __restrict__ W2,
                      const float* __restrict__ Wo) {
    constexpr int E1 = 6 * 3 * 512, E2 = 6 * 9 * 512, Eo = 9 * 512;
    int idx = blockIdx.x * blockDim.x + threadIdx.x;
    if (idx < E1)                wsplit4(W1, g_WB1, 43, 3, idx);
    else if (idx < E1 + E2)      wsplit4(W2, g_WB2, 134, 9, idx - E1);
    else if (idx < E1 + E2 + Eo) wsplit4(Wo, g_WBo, 134, 9, idx - E1 - E2);
}

// ============================ conv (mma.sync) ============================
template <int INF, int KUSED, int FS2, int WSEL, bool USE_EXT>
__global__ __launch_bounds__(256)
void conv_mma_kernel(const float* __restrict__ Xext,
                     const float* __restrict__ bonds,
                     const int*   __restrict__ edges,
                     const float* __restrict__ bias) {
    constexpr int KP2 = KUSED / 2;
    constexpr int NCH = KUSED / 16;
    __shared__ __align__(16) uint32_t fh[64 * FS2];
    __shared__ __align__(16) uint32_t fl[64 * FS2];
    __shared__ int satom[64];

    const float* __restrict__ X = USE_EXT ? Xext : (const float*)g_x2;
    const uint4* __restrict__ WB = (WSEL == 0) ? g_WB1 : g_WB2;

    int bid = blockIdx.x;
    if (bid >= g_tbase[7]) return;
    int deg = 0;
    #pragma unroll
    for (int d = 0; d < 6; d++) if (bid >= g_tbase[d + 1]) deg = d + 1;
    int cnt = g_bcnt[deg];
    int t0  = (bid - g_tbase[deg]) * 64;

    int tid = threadIdx.x, w = tid >> 5, lane = tid & 31;
    int tq = lane >> 2, tr = lane & 3;

    if (tid < 64) {
        int i = t0 + tid;
        satom[tid] = (i < cnt) ? g_bidx[deg * BN + i] : -1;
    }
    __syncthreads();

    if (deg >= DG) {      // deg==6 bucket (empty in practice): zero outputs
        for (int idx = tid; idx < 64 * 32; idx += 256) {
            int al = idx >> 5, q = idx & 31;
            int a = satom[al];
            if (a >= 0)
                *reinterpret_cast<float4*>(&g_x1[(size_t)a * HID + q * 4]) =
                    make_float4(0.f, 0.f, 0.f, 0.f);
        }
        return;
    }

    // ---- stage A: warp w handles atoms w*8 .. w*8+7 ----
    for (int j = 0; j < 8; j++) {
        int al = w * 8 + j;
        int a  = satom[al];
        int aa = (a >= 0) ? a : 0;
        int e = -1;
        if (lane < DG && a >= 0) e = edges[aa * DG + lane];
        int nb[DG];
        #pragma unroll
        for (int d = 0; d < DG; d++) nb[d] = __shfl_sync(FULL, e, d);
        int rowbase = (aa / NA) * NA;
        const float* xr = X + (size_t)aa * INF;

        for (int kp = lane; kp < KP2; kp += 32) {
            float s0 = 0.f, s1 = 0.f;
            if (a >= 0) {
                if ((INF % 2 == 0) && (2 * kp + 1 < INF)) {
                    float2 v = *reinterpret_cast<const float2*>(xr + 2 * kp);
                    s0 = v.x; s1 = v.y;
                    #pragma unroll
                    for (int d = 0; d < DG; d++)
                        if (nb[d] >= 0) {
                            float2 u = *reinterpret_cast<const float2*>(
                                X + (size_t)(rowbase + nb[d]) * INF + 2 * kp);
                            s0 += u.x; s1 += u.y;
                        }
                } else {
                    #pragma unroll
                    for (int h = 0; h < 2; h++) {
                        int k = 2 * kp + h;
                        float v = 0.f;
                        if (k < INF) {
                            v = xr[k];
                            #pragma unroll
                            for (int d = 0; d < DG; d++)
                                if (nb[d] >= 0) v += X[(size_t)(rowbase + nb[d]) * INF + k];
                        } else if (k < INF + BF) {
                            const float* bp = bonds + (size_t)aa * (DG * BF) + (k - INF);
                            v = bp[0] + bp[6] + bp[12] + bp[18] + bp[24] + bp[30];
                        }
                        if (h == 0) s0 = v; else s1 = v;
                    }
                }
            }
            __nv_bfloat16 h0 = __float2bfloat16(s0), h1 = __float2bfloat16(s1);
            fh[al * FS2 + kp] = (uint32_t)__bfloat16_as_ushort(h0) |
                                ((uint32_t)__bfloat16_as_ushort(h1) << 16);
            fl[al * FS2 + kp] = (uint32_t)bf16b(s0 - __bfloat162float(h0)) |
                                ((uint32_t)bf16b(s1 - __bfloat162float(h1)) << 16);
        }
    }
    __syncthreads();

    // ---- GEMM: warp w -> ch n0..n0+15; A via ldmatrix, B via uint4 LDG.128 ----
    int n0 = w * 16;
    float acc[4][2][4];
    #pragma unroll
    for (int m = 0; m < 4; m++)
        #pragma unroll
        for (int j = 0; j < 2; j++)
            #pragma unroll
            for (int q = 0; q < 4; q++) acc[m][j][q] = 0.f;

    const uint4* wb = WB + (size_t)deg * NCH * 512 + w * 64 + lane;

    uint32_t ah_base = smem_u32(fh) + 4 * ((lane & 15) * FS2 + (lane >> 4) * 4);
    uint32_t al_base = smem_u32(fl) + 4 * ((lane & 15) * FS2 + (lane >> 4) * 4);

    #pragma unroll
    for (int c = 0; c < NCH; c++) {
        uint32_t Ah[4][4], Al[4][4];
        #pragma unroll
        for (int m = 0; m < 4; m++) {
            uint32_t off = 4 * (m * 16 * FS2 + c * 8);
            LDSM_X4(Ah[m], ah_base + off);
            LDSM_X4(Al[m], al_base + off);
        }
        uint4 b0 = wb[c * 512];
        uint4 b1 = wb[c * 512 + 32];
        uint32_t Bh[2][2] = {{b0.x, b0.y}, {b1.x, b1.y}};
        uint32_t Bl[2][2] = {{b0.z, b0.w}, {b1.z, b1.w}};

        #pragma unroll
        for (int m = 0; m < 4; m++)
            #pragma unroll
            for (int j = 0; j < 2; j++) {
                mma16816(acc[m][j], Ah[m], Bh[j]);
                mma16816(acc[m][j], Al[m], Bh[j]);
                mma16816(acc[m][j], Ah[m], Bl[j]);
            }
    }

    // ---- epilogue: bias + relu, direct float2 stores ----
    float2 b2[2];
    #pragma unroll
    for (int j = 0; j < 2; j++) {
        int ch = n0 + j * 8 + 2 * tr;
        b2[j] = make_float2(bias[deg * HID + ch], bias[deg * HID + ch + 1]);
    }
    #pragma unroll
    for (int m = 0; m < 4; m++) {
        int a0 = satom[m * 16 + tq];
        int a1 = satom[m * 16 + tq + 8];
        #pragma unroll
        for (int j = 0; j < 2; j++) {
            int ch = n0 + j * 8 + 2 * tr;
            if (a0 >= 0)
                *reinterpret_cast<float2*>(&g_x1[(size_t)a0 * HID + ch]) =
                    make_float2(fmaxf(acc[m][j][0] + b2[j].x, 0.f),
                                fmaxf(acc[m][j][1] + b2[j].y, 0.f));
            if (a1 >= 0)
                *reinterpret_cast<float2*>(&g_x1[(size_t)a1 * HID + ch]) =
                    make_float2(fmaxf(acc[m][j][2] + b2[j].x, 0.f),
                                fmaxf(acc[m][j][3] + b2[j].y, 0.f));
        }
    }
}

// ============================ pool ============================
__global__ __launch_bounds__(256)
void pool_kernel(const int* __restrict__ edges) {
    int w = threadIdx.x >> 5, lane = threadIdx.x & 31;
    int a = blockIdx.x * 8 + w;
    int rowbase = (a / NA) * NA;
    int e = (lane < DG) ? edges[a * DG + lane] : -1;
    unsigned ball = __ballot_sync(FULL, e >= 0);
    int nb[DG];
    #pragma unroll
    for (int d = 0; d < DG; d++) nb[d] = __shfl_sync(FULL, e, d);
    int o = lane * 4;
    float4 v = *reinterpret_cast<const float4*>(g_x1 + (size_t)a * HID + o);
    #pragma unroll
    for (int d = 0; d < DG; d++) {
        if (nb[d] >= 0) {
            float4 u = *reinterpret_cast<const float4*>(g_x1 + (size_t)(rowbase + nb[d]) * HID + o);
            v.x = fmaxf(v.x, u.x); v.y = fmaxf(v.y, u.y);
            v.z = fmaxf(v.z, u.z); v.w = fmaxf(v.w, u.w);
        }
    }
    if (ball == 0u) v = make_float4(0.f, 0.f, 0.f, 0.f);
    *reinterpret_cast<float4*>(g_x2 + (size_t)a * HID + o) = v;
}

// ============================ gout (mma.sync) ============================
__global__ __launch_bounds__(256)
void gout_mma_kernel(const int*   __restrict__ edges,
                     const float* __restrict__ bonds,
                     const float* __restrict__ bo,
                     const float* __restrict__ Wfc,
                     const float* __restrict__ bfc,
                     float* __restrict__ out) {
    constexpr int KP2 = 72, NCH = 9, FS2 = 76;
    __shared__ __align__(16) uint32_t fh[64 * FS2];
    __shared__ __align__(16) uint32_t fl[64 * FS2];
    __shared__ float svalid[64];
    __shared__ float sfp[HID];

    int tid = threadIdx.x, w = tid >> 5, lane = tid & 31;
    int tq = lane >> 2, tr = lane & 3;
    int g = blockIdx.x;
    int rowbase = g * NA;

    // ---- stage A: inline pool2 + bondsum + validity ----
    for (int j = 0; j < 8; j++) {
        int al = w * 8 + j;
        bool ok = (al < NA);
        int a = rowbase + (ok ? al : 0);
        int e = -1;
        if (lane < DG && ok) e = edges[a * DG + lane];
        unsigned ball = __ballot_sync(FULL, e >= 0);
        int nb[DG];
        #pragma unroll
        for (int d = 0; d < DG; d++) nb[d] = __shfl_sync(FULL, e, d);
        bool valid = ok && (ball != 0u);

        for (int kp = lane; kp < KP2; kp += 32) {
            float s0 = 0.f, s1 = 0.f;
            if (valid) {
                if (2 * kp + 1 < HID) {
                    float2 v = *reinterpret_cast<const float2*>(g_x1 + (size_t)a * HID + 2 * kp);
                    #pragma unroll
                    for (int d = 0; d < DG; d++)
                        if (nb[d] >= 0) {
                            float2 u = *reinterpret_cast<const float2*>(
                                g_x1 + (size_t)(rowbase + nb[d]) * HID + 2 * kp);
                            v.x = fmaxf(v.x, u.x); v.y = fmaxf(v.y, u.y);
                        }
                    s0 = v.x; s1 = v.y;
                } else {
                    #pragma unroll
                    for (int h = 0; h < 2; h++) {
                        int k = 2 * kp + h;
                        float v = 0.f;
                        if (k < HID + BF && k >= HID) {
                            const float* bp = bonds + (size_t)a * (DG * BF) + (k - HID);
                            v = bp[0] + bp[6] + bp[12] + bp[18] + bp[24] + bp[30];
                        }
                        if (h == 0) s0 = v; else s1 = v;
                    }
                }
            }
            __nv_bfloat16 h0 = __float2bfloat16(s0), h1 = __float2bfloat16(s1);
            fh[al * FS2 + kp] = (uint32_t)__bfloat16_as_ushort(h0) |
                                ((uint32_t)__bfloat16_as_ushort(h1) << 16);
            fl[al * FS2 + kp] = (uint32_t)bf16b(s0 - __bfloat162float(h0)) |
                                ((uint32_t)bf16b(s1 - __bfloat162float(h1)) << 16);
        }
        if (lane == 0) svalid[al] = valid ? 1.f : 0.f;
    }
    __syncthreads();

    // ---- GEMM ----
    int n0 = w * 16;
    float acc[4][2][4];
    #pragma unroll
    for (int m = 0; m < 4; m++)
        #pragma unroll
        for (int j = 0; j < 2; j++)
            #pragma unroll
            for (int q = 0; q < 4; q++) acc[m][j][q] = 0.f;

    const uint4* wb = g_WBo + w * 64 + lane;

    uint32_t ah_base = smem_u32(fh) + 4 * ((lane & 15) * FS2 + (lane >> 4) * 4);
    uint32_t al_base = smem_u32(fl) + 4 * ((lane & 15) * FS2 + (lane >> 4) * 4);

    #pragma unroll
    for (int c = 0; c < NCH; c++) {
        uint32_t Ah[4][4], Al[4][4];
        #pragma unroll
        for (int m = 0; m < 4; m++) {
            uint32_t off = 4 * (m * 16 * FS2 + c * 8);
            LDSM_X4(Ah[m], ah_base + off);
            LDSM_X4(Al[m], al_base + off);
        }
        uint4 b0 = wb[c * 512];
        uint4 b1 = wb[c * 512 + 32];
        uint32_t Bh[2][2] = {{b0.x, b0.y}, {b1.x, b1.y}};
        uint32_t Bl[2][2] = {{b0.z, b0.w}, {b1.z, b1.w}};

        #pragma unroll
        for (int m = 0; m < 4; m++)
            #pragma unroll
            for (int j = 0; j < 2; j++) {
                mma16816(acc[m][j], Ah[m], Bh[j]);
                mma16816(acc[m][j], Al[m], Bh[j]);
                mma16816(acc[m][j], Ah[m], Bl[j]);
            }
    }

    // ---- epilogue: bias + tanh + mask, reduce over atoms ----
    float2 b2[2];
    #pragma unroll
    for (int j = 0; j < 2; j++) {
        int ch = n0 + j * 8 + 2 * tr;
        b2[j] = make_float2(bo[ch], bo[ch + 1]);
    }
    float cs[2][2] = {{0.f, 0.f}, {0.f, 0.f}};
    #pragma unroll
    for (int m = 0; m < 4; m++) {
        float v0 = svalid[m * 16 + tq];
        float v1 = svalid[m * 16 + tq + 8];
        #pragma unroll
        for (int j = 0; j < 2; j++) {
            cs[j][0] += v0 * htanh(acc[m][j][0] + b2[j].x)
                      + v1 * htanh(acc[m][j][2] + b2[j].x);
            cs[j][1] += v0 * htanh(acc[m][j][1] + b2[j].y)
                      + v1 * htanh(acc[m][j][3] + b2[j].y);
        }
    }
    #pragma unroll
    for (int off = 4; off < 32; off <<= 1) {
        #pragma unroll
        for (int j = 0; j < 2; j++) {
            cs[j][0] += __shfl_xor_sync(FULL, cs[j][0], off);
            cs[j][1] += __shfl_xor_sync(FULL, cs[j][1], off);
        }
    }
    if (tq == 0) {
        #pragma unroll
        for (int j = 0; j < 2; j++) {
            int ch = n0 + j * 8 + 2 * tr;
            sfp[ch]     = cs[j][0];
            sfp[ch + 1] = cs[j][1];
        }
    }
    __syncthreads();

    if (tid < NC) {
        float v = bfc[tid];
        #pragma unroll 8
        for (int o = 0; o < HID; o++) v = fmaf(sfp[o], Wfc[o * NC + tid], v);
        out[g * NC + tid] = 1.0f / (1.0f + expf(-v));
    }
}

// ---------------------------------------------------------------------------
extern "C" void kernel_launch(void* const* d_in, const int* in_sizes, int n_in,
                              void* d_out, int out_size) {
    const float* atoms = (const float*)d_in[0];
    const float* bonds = (const float*)d_in[1];
    const int*   edges = (const int*)  d_in[2];
    const float* W1    = (const float*)d_in[3];
    const float* b1    = (const float*)d_in[4];
    const float* W2    = (const float*)d_in[5];
    const float* b2    = (const float*)d_in[6];
    const float* Wo    = (const float*)d_in[7];
    const float* bo    = (const float*)d_in[8];
    const float* Wfc   = (const float*)d_in[9];
    const float* bfc   = (const float*)d_in[10];
    float* out = (float*)d_out;

    bucketA_kernel<<<NCHK, 256>>>(edges);
    bucketB_kernel<<<1, 224>>>();
    bucketC_kernel<<<NCHK, 256>>>();
    wprep_all_kernel<<<(6*3*512 + 6*9*512 + 9*512 + 255) / 256, 256>>>(W1, W2, Wo);

    conv_mma_kernel<AF, 48, 28, 0, true><<<MAXT, 256>>>(atoms, bonds, edges, b1);
    pool_kernel<<<BN / 8, 256>>>(edges);
    conv_mma_kernel<HID, 144, 76, 1, false><<<MAXT, 256>>>(nullptr, bonds, edges, b2);
    gout_mma_kernel<<<B, 256>>>(edges, bonds, bo, Wfc, bfc, out);
}

// round 13
// speedup vs baseline: 1.2963x; 1.2963x over previous
#include <cuda_runtime.h>
#include <cuda_bf16.h>
#include <cstdint>

#define FULL 0xFFFFFFFFu

constexpr int B   = 2048;
constexpr int NA  = 60;
constexpr int DG  = 6;
constexpr int AF  = 37;
constexpr int BF  = 6;
constexpr int HID = 128;
constexpr int NC  = 12;
constexpr int BN  = B * NA;
constexpr int MAXT = 1926;          // max total conv tiles: 122880/64 + 6

// ---- scratch (allocation-free) ----
__device__ float    g_x1[BN * HID];
__device__ float    g_x2[BN * HID];
__device__ int      g_bidx[7 * BN];
__device__ int      g_bcnt[8];
__device__ int      g_tbase[8];     // exclusive tile prefix per degree
// B-fragment-packed weights: entry (deg,c,w,j,lane) -> uint4{hi@kp0,hi@kp1,lo@kp0,lo@kp1}
__device__ uint4    g_WB1[6 * 3 * 512];
__device__ uint4    g_WB2[6 * 9 * 512];
__device__ uint4    g_WBo[9 * 512];

__device__ __forceinline__ float htanh(float x) {
    float y; asm("tanh.approx.f32 %0, %1;" : "=f"(y) : "f"(x)); return y;
}
__device__ __forceinline__ uint16_t bf16b(float x) {
    return __bfloat16_as_ushort(__float2bfloat16(x));
}
__device__ __forceinline__ uint32_t smem_u32(const void* p) {
    uint32_t a;
    asm("{ .reg .u64 t; cvta.to.shared.u64 t, %1; cvt.u32.u64 %0, t; }" : "=r"(a) : "l"(p));
    return a;
}
__device__ __forceinline__ void mma16816(float* d, const uint32_t* a, const uint32_t* b) {
    asm volatile("mma.sync.aligned.m16n8k16.row.col.f32.bf16.bf16.f32 "
                 "{%0,%1,%2,%3}, {%4,%5,%6,%7}, {%8,%9}, {%0,%1,%2,%3};"
                 : "+f"(d[0]), "+f"(d[1]), "+f"(d[2]), "+f"(d[3])
                 : "r"(a[0]), "r"(a[1]), "r"(a[2]), "r"(a[3]), "r"(b[0]), "r"(b[1]));
}
#define LDSM_X4(r, a) \
    asm volatile("ldmatrix.sync.aligned.m8n8.x4.shared.b16 {%0,%1,%2,%3}, [%4];" \
                 : "=r"((r)[0]), "=r"((r)[1]), "=r"((r)[2]), "=r"((r)[3]) : "r"(a))

// ============================ prep (R10 atomicAdd version) ============================
__global__ void zero_cnt_kernel() { if (threadIdx.x < 8) g_bcnt[threadIdx.x] = 0; }

__global__ __launch_bounds__(256)
void prep_kernel(const int* __restrict__ edges) {
    int a = blockIdx.x * blockDim.x + threadIdx.x;
    if (a >= BN) return;
    int deg = 0;
    #pragma unroll
    for (int d = 0; d < DG; d++) deg += (edges[a * DG + d] >= 0);
    int pos = atomicAdd(&g_bcnt[deg], 1);
    g_bidx[deg * BN + pos] = a;
}

__global__ void tileprep_kernel() {
    if (threadIdx.x == 0) {
        int s = 0;
        #pragma unroll
        for (int d = 0; d < 7; d++) { g_tbase[d] = s; s += (g_bcnt[d] + 63) >> 6; }
        g_tbase[7] = s;
    }
}

// ==================== weight repack (B-fragment uint4 layout) ====================
__device__ __forceinline__ void wsplit4(const float* __restrict__ W, uint4* dst,
                                        int IN, int NCH, int sub) {
    int lane = sub & 31;
    int j    = (sub >> 5) & 1;
    int w    = (sub >> 6) & 7;
    int rest = sub >> 9;
    int c    = rest % NCH;
    int deg  = rest / NCH;
    int tq = lane >> 2, tr = lane & 3;
    int ch  = w * 16 + j * 8 + tq;
    int kp0 = c * 8 + tr, kp1 = kp0 + 4;

    uint32_t ww[4];
    #pragma unroll
    for (int q = 0; q < 2; q++) {
        int kp = q ? kp1 : kp0;
        int k0 = 2 * kp, k1 = 2 * kp + 1;
        float w0 = (k0 < IN) ? W[(deg * IN + k0) * HID + ch] : 0.f;
        float w1 = (k1 < IN) ? W[(deg * IN + k1) * HID + ch] : 0.f;
        __nv_bfloat16 h0 = __float2bfloat16(w0), h1 = __float2bfloat16(w1);
        ww[q]     = (uint32_t)__bfloat16_as_ushort(h0) |
                    ((uint32_t)__bfloat16_as_ushort(h1) << 16);
        ww[2 + q] = (uint32_t)bf16b(w0 - __bfloat162float(h0)) |
                    ((uint32_t)bf16b(w1 - __bfloat162float(h1)) << 16);
    }
    dst[sub] = make_uint4(ww[0], ww[1], ww[2], ww[3]);
}

__global__ __launch_bounds__(256)
void wprep_all_kernel(const float* __restrict__ W1, const float* __restrict__ W2,
                      const float* __restrict__ Wo) {
    constexpr int E1 = 6 * 3 * 512, E2 = 6 * 9 * 512, Eo = 9 * 512;
    int idx = blockIdx.x * blockDim.x + threadIdx.x;
    if (idx < E1)                wsplit4(W1, g_WB1, 43, 3, idx);
    else if (idx < E1 + E2)      wsplit4(W2, g_WB2, 134, 9, idx - E1);
    else if (idx < E1 + E2 + Eo) wsplit4(Wo, g_WBo, 134, 9, idx - E1 - E2);
}

// ============================ conv (mma.sync) ============================
template <int INF, int KUSED, int FS2, int WSEL, bool USE_EXT>
__global__ __launch_bounds__(256)
void conv_mma_kernel(const float* __restrict__ Xext,
                     const float* __restrict__ bonds,
                     const int*   __restrict__ edges,
                     const float* __restrict__ bias) {
    constexpr int KP2 = KUSED / 2;
    constexpr int NCH = KUSED / 16;
    __shared__ __align__(16) uint32_t fh[64 * FS2];
    __shared__ __align__(16) uint32_t fl[64 * FS2];
    __shared__ int satom[64];

    const float* __restrict__ X = USE_EXT ? Xext : (const float*)g_x2;
    const uint4* __restrict__ WB = (WSEL == 0) ? g_WB1 : g_WB2;

    int bid = blockIdx.x;
    if (bid >= g_tbase[7]) return;
    int deg = 0;
    #pragma unroll
    for (int d = 0; d < 6; d++) if (bid >= g_tbase[d + 1]) deg = d + 1;
    int cnt = g_bcnt[deg];
    int t0  = (bid - g_tbase[deg]) * 64;

    int tid = threadIdx.x, w = tid >> 5, lane = tid & 31;
    int tq = lane >> 2, tr = lane & 3;

    if (tid < 64) {
        int i = t0 + tid;
        satom[tid] = (i < cnt) ? g_bidx[deg * BN + i] : -1;
    }
    __syncthreads();

    if (deg >= DG) {      // deg==6 bucket (empty in practice): zero outputs
        for (int idx = tid; idx < 64 * 32; idx += 256) {
            int al = idx >> 5, q = idx & 31;
            int a = satom[al];
            if (a >= 0)
                *reinterpret_cast<float4*>(&g_x1[(size_t)a * HID + q * 4]) =
                    make_float4(0.f, 0.f, 0.f, 0.f);
        }
        return;
    }

    // ---- stage A: warp w handles atoms w*8 .. w*8+7 ----
    for (int j = 0; j < 8; j++) {
        int al = w * 8 + j;
        int a  = satom[al];
        int aa = (a >= 0) ? a : 0;
        int e = -1;
        if (lane < DG && a >= 0) e = edges[aa * DG + lane];
        int nb[DG];
        #pragma unroll
        for (int d = 0; d < DG; d++) nb[d] = __shfl_sync(FULL, e, d);
        int rowbase = (aa / NA) * NA;
        const float* xr = X + (size_t)aa * INF;

        for (int kp = lane; kp < KP2; kp += 32) {
            float s0 = 0.f, s1 = 0.f;
            if (a >= 0) {
                if ((INF % 2 == 0) && (2 * kp + 1 < INF)) {
                    float2 v = *reinterpret_cast<const float2*>(xr + 2 * kp);
                    s0 = v.x; s1 = v.y;
                    #pragma unroll
                    for (int d = 0; d < DG; d++)
                        if (nb[d] >= 0) {
                            float2 u = *reinterpret_cast<const float2*>(
                                X + (size_t)(rowbase + nb[d]) * INF + 2 * kp);
                            s0 += u.x; s1 += u.y;
                        }
                } else {
                    #pragma unroll
                    for (int h = 0; h < 2; h++) {
                        int k = 2 * kp + h;
                        float v = 0.f;
                        if (k < INF) {
                            v = xr[k];
                            #pragma unroll
                            for (int d = 0; d < DG; d++)
                                if (nb[d] >= 0) v += X[(size_t)(rowbase + nb[d]) * INF + k];
                        } else if (k < INF + BF) {
                            const float* bp = bonds + (size_t)aa * (DG * BF) + (k - INF);
                            v = bp[0] + bp[6] + bp[12] + bp[18] + bp[24] + bp[30];
                        }
                        if (h == 0) s0 = v; else s1 = v;
                    }
                }
            }
            __nv_bfloat16 h0 = __float2bfloat16(s0), h1 = __float2bfloat16(s1);
            fh[al * FS2 + kp] = (uint32_t)__bfloat16_as_ushort(h0) |
                                ((uint32_t)__bfloat16_as_ushort(h1) << 16);
            fl[al * FS2 + kp] = (uint32_t)bf16b(s0 - __bfloat162float(h0)) |
                                ((uint32_t)bf16b(s1 - __bfloat162float(h1)) << 16);
        }
    }
    __syncthreads();

    // ---- GEMM: warp w -> ch n0..n0+15; A via ldmatrix, B via uint4 LDG.128 ----
    int n0 = w * 16;
    float acc[4][2][4];
    #pragma unroll
    for (int m = 0; m < 4; m++)
        #pragma unroll
        for (int j = 0; j < 2; j++)
            #pragma unroll
            for (int q = 0; q < 4; q++) acc[m][j][q] = 0.f;

    const uint4* wb = WB + (size_t)deg * NCH * 512 + w * 64 + lane;

    uint32_t ah_base = smem_u32(fh) + 4 * ((lane & 15) * FS2 + (lane >> 4) * 4);
    uint32_t al_base = smem_u32(fl) + 4 * ((lane & 15) * FS2 + (lane >> 4) * 4);

    #pragma unroll
    for (int c = 0; c < NCH; c++) {
        uint32_t Ah[4][4], Al[4][4];
        #pragma unroll
        for (int m = 0; m < 4; m++) {
            uint32_t off = 4 * (m * 16 * FS2 + c * 8);
            LDSM_X4(Ah[m], ah_base + off);
            LDSM_X4(Al[m], al_base + off);
        }
        uint4 b0 = wb[c * 512];
        uint4 b1 = wb[c * 512 + 32];
        uint32_t Bh[2][2] = {{b0.x, b0.y}, {b1.x, b1.y}};
        uint32_t Bl[2][2] = {{b0.z, b0.w}, {b1.z, b1.w}};

        #pragma unroll
        for (int m = 0; m < 4; m++)
            #pragma unroll
            for (int j = 0; j < 2; j++) {
                mma16816(acc[m][j], Ah[m], Bh[j]);
                mma16816(acc[m][j], Al[m], Bh[j]);
                mma16816(acc[m][j], Ah[m], Bl[j]);
            }
    }

    // ---- epilogue: bias + relu, direct float2 stores ----
    float2 b2[2];
    #pragma unroll
    for (int j = 0; j < 2; j++) {
        int ch = n0 + j * 8 + 2 * tr;
        b2[j] = make_float2(bias[deg * HID + ch], bias[deg * HID + ch + 1]);
    }
    #pragma unroll
    for (int m = 0; m < 4; m++) {
        int a0 = satom[m * 16 + tq];
        int a1 = satom[m * 16 + tq + 8];
        #pragma unroll
        for (int j = 0; j < 2; j++) {
            int ch = n0 + j * 8 + 2 * tr;
            if (a0 >= 0)
                *reinterpret_cast<float2*>(&g_x1[(size_t)a0 * HID + ch]) =
                    make_float2(fmaxf(acc[m][j][0] + b2[j].x, 0.f),
                                fmaxf(acc[m][j][1] + b2[j].y, 0.f));
            if (a1 >= 0)
                *reinterpret_cast<float2*>(&g_x1[(size_t)a1 * HID + ch]) =
                    make_float2(fmaxf(acc[m][j][2] + b2[j].x, 0.f),
                                fmaxf(acc[m][j][3] + b2[j].y, 0.f));
        }
    }
}

// ============================ pool ============================
__global__ __launch_bounds__(256)
void pool_kernel(const int* __restrict__ edges) {
    int w = threadIdx.x >> 5, lane = threadIdx.x & 31;
    int a = blockIdx.x * 8 + w;
    int rowbase = (a / NA) * NA;
    int e = (lane < DG) ? edges[a * DG + lane] : -1;
    unsigned ball = __ballot_sync(FULL, e >= 0);
    int nb[DG];
    #pragma unroll
    for (int d = 0; d < DG; d++) nb[d] = __shfl_sync(FULL, e, d);
    int o = lane * 4;
    float4 v = *reinterpret_cast<const float4*>(g_x1 + (size_t)a * HID + o);
    #pragma unroll
    for (int d = 0; d < DG; d++) {
        if (nb[d] >= 0) {
            float4 u = *reinterpret_cast<const float4*>(g_x1 + (size_t)(rowbase + nb[d]) * HID + o);
            v.x = fmaxf(v.x, u.x); v.y = fmaxf(v.y, u.y);
            v.z = fmaxf(v.z, u.z); v.w = fmaxf(v.w, u.w);
        }
    }
    if (ball == 0u) v = make_float4(0.f, 0.f, 0.f, 0.f);
    *reinterpret_cast<float4*>(g_x2 + (size_t)a * HID + o) = v;
}

// ============================ gout (mma.sync) ============================
__global__ __launch_bounds__(256)
void gout_mma_kernel(const int*   __restrict__ edges,
                     const float* __restrict__ bonds,
                     const float* __restrict__ bo,
                     const float* __restrict__ Wfc,
                     const float* __restrict__ bfc,
                     float* __restrict__ out) {
    constexpr int KP2 = 72, NCH = 9, FS2 = 76;
    __shared__ __align__(16) uint32_t fh[64 * FS2];
    __shared__ __align__(16) uint32_t fl[64 * FS2];
    __shared__ float svalid[64];
    __shared__ float sfp[HID];

    int tid = threadIdx.x, w = tid >> 5, lane = tid & 31;
    int tq = lane >> 2, tr = lane & 3;
    int g = blockIdx.x;
    int rowbase = g * NA;

    // ---- stage A: inline pool2 + bondsum + validity ----
    for (int j = 0; j < 8; j++) {
        int al = w * 8 + j;
        bool ok = (al < NA);
        int a = rowbase + (ok ? al : 0);
        int e = -1;
        if (lane < DG && ok) e = edges[a * DG + lane];
        unsigned ball = __ballot_sync(FULL, e >= 0);
        int nb[DG];
        #pragma unroll
        for (int d = 0; d < DG; d++) nb[d] = __shfl_sync(FULL, e, d);
        bool valid = ok && (ball != 0u);

        for (int kp = lane; kp < KP2; kp += 32) {
            float s0 = 0.f, s1 = 0.f;
            if (valid) {
                if (2 * kp + 1 < HID) {
                    float2 v = *reinterpret_cast<const float2*>(g_x1 + (size_t)a * HID + 2 * kp);
                    #pragma unroll
                    for (int d = 0; d < DG; d++)
                        if (nb[d] >= 0) {
                            float2 u = *reinterpret_cast<const float2*>(
                                g_x1 + (size_t)(rowbase + nb[d]) * HID + 2 * kp);
                            v.x = fmaxf(v.x, u.x); v.y = fmaxf(v.y, u.y);
                        }
                    s0 = v.x; s1 = v.y;
                } else {
                    #pragma unroll
                    for (int h = 0; h < 2; h++) {
                        int k = 2 * kp + h;
                        float v = 0.f;
                        if (k < HID + BF && k >= HID) {
                            const float* bp = bonds + (size_t)a * (DG * BF) + (k - HID);
                            v = bp[0] + bp[6] + bp[12] + bp[18] + bp[24] + bp[30];
                        }
                        if (h == 0) s0 = v; else s1 = v;
                    }
                }
            }
            __nv_bfloat16 h0 = __float2bfloat16(s0), h1 = __float2bfloat16(s1);
            fh[al * FS2 + kp] = (uint32_t)__bfloat16_as_ushort(h0) |
                                ((uint32_t)__bfloat16_as_ushort(h1) << 16);
            fl[al * FS2 + kp] = (uint32_t)bf16b(s0 - __bfloat162float(h0)) |
                                ((uint32_t)bf16b(s1 - __bfloat162float(h1)) << 16);
        }
        if (lane == 0) svalid[al] = valid ? 1.f : 0.f;
    }
    __syncthreads();

    // ---- GEMM ----
    int n0 = w * 16;
    float acc[4][2][4];
    #pragma unroll
    for (int m = 0; m < 4; m++)
        #pragma unroll
        for (int j = 0; j < 2; j++)
            #pragma unroll
            for (int q = 0; q < 4; q++) acc[m][j][q] = 0.f;

    const uint4* wb = g_WBo + w * 64 + lane;

    uint32_t ah_base = smem_u32(fh) + 4 * ((lane & 15) * FS2 + (lane >> 4) * 4);
    uint32_t al_base = smem_u32(fl) + 4 * ((lane & 15) * FS2 + (lane >> 4) * 4);

    #pragma unroll
    for (int c = 0; c < NCH; c++) {
        uint32_t Ah[4][4], Al[4][4];
        #pragma unroll
        for (int m = 0; m < 4; m++) {
            uint32_t off = 4 * (m * 16 * FS2 + c * 8);
            LDSM_X4(Ah[m], ah_base + off);
            LDSM_X4(Al[m], al_base + off);
        }
        uint4 b0 = wb[c * 512];
        uint4 b1 = wb[c * 512 + 32];
        uint32_t Bh[2][2] = {{b0.x, b0.y}, {b1.x, b1.y}};
        uint32_t Bl[2][2] = {{b0.z, b0.w}, {b1.z, b1.w}};

        #pragma unroll
        for (int m = 0; m < 4; m++)
            #pragma unroll
            for (int j = 0; j < 2; j++) {
                mma16816(acc[m][j], Ah[m], Bh[j]);
                mma16816(acc[m][j], Al[m], Bh[j]);
                mma16816(acc[m][j], Ah[m], Bl[j]);
            }
    }

    // ---- epilogue: bias + tanh + mask, reduce over atoms ----
    float2 b2[2];
    #pragma unroll
    for (int j = 0; j < 2; j++) {
        int ch = n0 + j * 8 + 2 * tr;
        b2[j] = make_float2(bo[ch], bo[ch + 1]);
    }
    float cs[2][2] = {{0.f, 0.f}, {0.f, 0.f}};
    #pragma unroll
    for (int m = 0; m < 4; m++) {
        float v0 = svalid[m * 16 + tq];
        float v1 = svalid[m * 16 + tq + 8];
        #pragma unroll
        for (int j = 0; j < 2; j++) {
            cs[j][0] += v0 * htanh(acc[m][j][0] + b2[j].x)
                      + v1 * htanh(acc[m][j][2] + b2[j].x);
            cs[j][1] += v0 * htanh(acc[m][j][1] + b2[j].y)
                      + v1 * htanh(acc[m][j][3] + b2[j].y);
        }
    }
    #pragma unroll
    for (int off = 4; off < 32; off <<= 1) {
        #pragma unroll
        for (int j = 0; j < 2; j++) {
            cs[j][0] += __shfl_xor_sync(FULL, cs[j][0], off);
            cs[j][1] += __shfl_xor_sync(FULL, cs[j][1], off);
        }
    }
    if (tq == 0) {
        #pragma unroll
        for (int j = 0; j < 2; j++) {
            int ch = n0 + j * 8 + 2 * tr;
            sfp[ch]     = cs[j][0];
            sfp[ch + 1] = cs[j][1];
        }
    }
    __syncthreads();

    if (tid < NC) {
        float v = bfc[tid];
        #pragma unroll 8
        for (int o = 0; o < HID; o++) v = fmaf(sfp[o], Wfc[o * NC + tid], v);
        out[g * NC + tid] = 1.0f / (1.0f + expf(-v));
    }
}

// ---------------------------------------------------------------------------
extern "C" void kernel_launch(void* const* d_in, const int* in_sizes, int n_in,
                              void* d_out, int out_size) {
    const float* atoms = (const float*)d_in[0];
    const float* bonds = (const float*)d_in[1];
    const int*   edges = (const int*)  d_in[2];
    const float* W1    = (const float*)d_in[3];
    const float* b1    = (const float*)d_in[4];
    const float* W2    = (const float*)d_in[5];
    const float* b2    = (const float*)d_in[6];
    const float* Wo    = (const float*)d_in[7];
    const float* bo    = (const float*)d_in[8];
    const float* Wfc   = (const float*)d_in[9];
    const float* bfc   = (const float*)d_in[10];
    float* out = (float*)d_out;

    zero_cnt_kernel<<<1, 32>>>();
    prep_kernel<<<BN / 256, 256>>>(edges);
    tileprep_kernel<<<1, 32>>>();
    wprep_all_kernel<<<(6*3*512 + 6*9*512 + 9*512 + 255) / 256, 256>>>(W1, W2, Wo);

    conv_mma_kernel<AF, 48, 28, 0, true><<<MAXT, 256>>>(atoms, bonds, edges, b1);
    pool_kernel<<<BN / 8, 256>>>(edges);
    conv_mma_kernel<HID, 144, 76, 1, false><<<MAXT, 256>>>(nullptr, bonds, edges, b2);
    gout_mma_kernel<<<B, 256>>>(edges, bonds, bo, Wfc, bfc, out);
}

// round 14
// speedup vs baseline: 1.4691x; 1.1333x over previous
#include <cuda_runtime.h>
#include <cuda_bf16.h>
#include <cstdint>

#define FULL 0xFFFFFFFFu

constexpr int B   = 2048;
constexpr int NA  = 60;
constexpr int DG  = 6;
constexpr int AF  = 37;
constexpr int BF  = 6;
constexpr int HID = 128;
constexpr int NC  = 12;
constexpr int BN  = B * NA;
constexpr int MAXT = 1926;          // max total conv tiles: 122880/64 + 6

// ---- scratch (allocation-free) ----
__device__ float    g_x1[BN * HID];
__device__ float    g_x2[BN * HID];
__device__ int      g_bidx[7 * BN];
__device__ int      g_bcnt[8];
// B-fragment-packed weights: entry (deg,c,w,j,lane) -> uint4{hi@kp0,hi@kp1,lo@kp0,lo@kp1}
__device__ uint4    g_WB1[6 * 3 * 512];
__device__ uint4    g_WB2[6 * 9 * 512];
__device__ uint4    g_WBo[9 * 512];

__device__ __forceinline__ float htanh(float x) {
    float y; asm("tanh.approx.f32 %0, %1;" : "=f"(y) : "f"(x)); return y;
}
__device__ __forceinline__ uint16_t bf16b(float x) {
    return __bfloat16_as_ushort(__float2bfloat16(x));
}
__device__ __forceinline__ uint32_t smem_u32(const void* p) {
    uint32_t a;
    asm("{ .reg .u64 t; cvta.to.shared.u64 t, %1; cvt.u32.u64 %0, t; }" : "=r"(a) : "l"(p));
    return a;
}
__device__ __forceinline__ uint32_t packbf(float s0, float s1) {
    __nv_bfloat16 h0 = __float2bfloat16(s0), h1 = __float2bfloat16(s1);
    return (uint32_t)__bfloat16_as_ushort(h0) | ((uint32_t)__bfloat16_as_ushort(h1) << 16);
}
__device__ __forceinline__ uint32_t packlo(float s0, float s1) {
    __nv_bfloat16 h0 = __float2bfloat16(s0), h1 = __float2bfloat16(s1);
    return (uint32_t)bf16b(s0 - __bfloat162float(h0)) |
           ((uint32_t)bf16b(s1 - __bfloat162float(h1)) << 16);
}
__device__ __forceinline__ void mma16816(float* d, const uint32_t* a, const uint32_t* b) {
    asm volatile("mma.sync.aligned.m16n8k16.row.col.f32.bf16.bf16.f32 "
                 "{%0,%1,%2,%3}, {%4,%5,%6,%7}, {%8,%9}, {%0,%1,%2,%3};"
                 : "+f"(d[0]), "+f"(d[1]), "+f"(d[2]), "+f"(d[3])
                 : "r"(a[0]), "r"(a[1]), "r"(a[2]), "r"(a[3]), "r"(b[0]), "r"(b[1]));
}
#define LDSM_X4(r, a) \
    asm volatile("ldmatrix.sync.aligned.m8n8.x4.shared.b16 {%0,%1,%2,%3}, [%4];" \
                 : "=r"((r)[0]), "=r"((r)[1]), "=r"((r)[2]), "=r"((r)[3]) : "r"(a))

// ============================ prep ============================
__global__ void zero_cnt_kernel() { if (threadIdx.x < 8) g_bcnt[threadIdx.x] = 0; }

__global__ __launch_bounds__(256)
void prep_kernel(const int* __restrict__ edges) {
    int a = blockIdx.x * blockDim.x + threadIdx.x;
    if (a >= BN) return;
    int deg = 0;
    #pragma unroll
    for (int d = 0; d < DG; d++) deg += (edges[a * DG + d] >= 0);
    int pos = atomicAdd(&g_bcnt[deg], 1);
    g_bidx[deg * BN + pos] = a;
}

// ==================== weight repack (B-fragment uint4 layout) ====================
__device__ __forceinline__ void wsplit4(const float* __restrict__ W, uint4* dst,
                                        int IN, int NCH, int sub) {
    int lane = sub & 31;
    int j    = (sub >> 5) & 1;
    int w    = (sub >> 6) & 7;
    int rest = sub >> 9;
    int c    = rest % NCH;
    int deg  = rest / NCH;
    int tq = lane >> 2, tr = lane & 3;
    int ch  = w * 16 + j * 8 + tq;
    int kp0 = c * 8 + tr, kp1 = kp0 + 4;

    uint32_t ww[4];
    #pragma unroll
    for (int q = 0; q < 2; q++) {
        int kp = q ? kp1 : kp0;
        int k0 = 2 * kp, k1 = 2 * kp + 1;
        float w0 = (k0 < IN) ? W[(deg * IN + k0) * HID + ch] : 0.f;
        float w1 = (k1 < IN) ? W[(deg * IN + k1) * HID + ch] : 0.f;
        __nv_bfloat16 h0 = __float2bfloat16(w0), h1 = __float2bfloat16(w1);
        ww[q]     = (uint32_t)__bfloat16_as_ushort(h0) |
                    ((uint32_t)__bfloat16_as_ushort(h1) << 16);
        ww[2 + q] = (uint32_t)bf16b(w0 - __bfloat162float(h0)) |
                    ((uint32_t)bf16b(w1 - __bfloat162float(h1)) << 16);
    }
    dst[sub] = make_uint4(ww[0], ww[1], ww[2], ww[3]);
}

__global__ __launch_bounds__(256)
void wprep_all_kernel(const float* __restrict__ W1, const float* __restrict__ W2,
                      const float* __restrict__ Wo) {
    constexpr int E1 = 6 * 3 * 512, E2 = 6 * 9 * 512, Eo = 9 * 512;
    int idx = blockIdx.x * blockDim.x + threadIdx.x;
    if (idx < E1)                wsplit4(W1, g_WB1, 43, 3, idx);
    else if (idx < E1 + E2)      wsplit4(W2, g_WB2, 134, 9, idx - E1);
    else if (idx < E1 + E2 + Eo) wsplit4(Wo, g_WBo, 134, 9, idx - E1 - E2);
}

// ============================ conv (mma.sync) ============================
template <int INF, int KUSED, int FS2, int WSEL, bool USE_EXT>
__global__ __launch_bounds__(256)
void conv_mma_kernel(const float* __restrict__ Xext,
                     const float* __restrict__ bonds,
                     const int*   __restrict__ edges,
                     const float* __restrict__ bias) {
    constexpr int KP2 = KUSED / 2;
    constexpr int NCH = KUSED / 16;
    __shared__ __align__(16) uint32_t fh[64 * FS2];
    __shared__ __align__(16) uint32_t fl[64 * FS2];
    __shared__ int satom[64];

    const float* __restrict__ X = USE_EXT ? Xext : (const float*)g_x2;
    const uint4* __restrict__ WB = (WSEL == 0) ? g_WB1 : g_WB2;

    // in-register tile prefix over g_bcnt (replaces tileprep kernel)
    int bid = blockIdx.x;
    int deg = 0, tb = 0, acc = 0;
    #pragma unroll
    for (int d = 0; d < 7; d++) {
        int nt = (g_bcnt[d] + 63) >> 6;
        if (bid >= acc && bid < acc + nt) { deg = d; tb = acc; }
        acc += nt;
    }
    if (bid >= acc) return;
    int cnt = g_bcnt[deg];
    int t0  = (bid - tb) * 64;

    int tid = threadIdx.x, w = tid >> 5, lane = tid & 31;
    int tq = lane >> 2, tr = lane & 3;

    if (tid < 64) {
        int i = t0 + tid;
        satom[tid] = (i < cnt) ? g_bidx[deg * BN + i] : -1;
    }
    __syncthreads();

    if (deg >= DG) {      // deg==6 bucket (empty in practice): zero outputs
        for (int idx = tid; idx < 64 * 32; idx += 256) {
            int al = idx >> 5, q = idx & 31;
            int a = satom[al];
            if (a >= 0)
                *reinterpret_cast<float4*>(&g_x1[(size_t)a * HID + q * 4]) =
                    make_float4(0.f, 0.f, 0.f, 0.f);
        }
        return;
    }

    // ---- stage A: warp w handles atoms w*8 .. w*8+7 ----
    for (int j = 0; j < 8; j++) {
        int al = w * 8 + j;
        int a  = satom[al];
        int aa = (a >= 0) ? a : 0;
        int e = -1;
        if (lane < DG && a >= 0) e = edges[aa * DG + lane];
        int nb[DG];
        #pragma unroll
        for (int d = 0; d < DG; d++) nb[d] = __shfl_sync(FULL, e, d);
        int rowbase = (aa / NA) * NA;
        const float* xr = X + (size_t)aa * INF;

        if constexpr (INF == HID) {
            // fast path: one float4 per lane covers kp = 2*lane, 2*lane+1
            float4 v = make_float4(0.f, 0.f, 0.f, 0.f);
            if (a >= 0) {
                v = *reinterpret_cast<const float4*>(xr + 4 * lane);
                #pragma unroll
                for (int d = 0; d < DG; d++)
                    if (nb[d] >= 0) {
                        float4 u = *reinterpret_cast<const float4*>(
                            X + (size_t)(rowbase + nb[d]) * HID + 4 * lane);
                        v.x += u.x; v.y += u.y; v.z += u.z; v.w += u.w;
                    }
            }
            int kp0 = 2 * lane;
            *reinterpret_cast<uint2*>(&fh[al * FS2 + kp0]) =
                make_uint2(packbf(v.x, v.y), packbf(v.z, v.w));
            *reinterpret_cast<uint2*>(&fl[al * FS2 + kp0]) =
                make_uint2(packlo(v.x, v.y), packlo(v.z, v.w));
            if (lane < 8) {
                int kp = 64 + lane;
                float s0 = 0.f, s1 = 0.f;
                if (a >= 0) {
                    int f0 = 2 * lane, f1 = 2 * lane + 1;   // bond features
                    if (f0 < BF) {
                        const float* bp = bonds + (size_t)aa * (DG * BF) + f0;
                        s0 = bp[0] + bp[6] + bp[12] + bp[18] + bp[24] + bp[30];
                    }
                    if (f1 < BF) {
                        const float* bp = bonds + (size_t)aa * (DG * BF) + f1;
                        s1 = bp[0] + bp[6] + bp[12] + bp[18] + bp[24] + bp[30];
                    }
                }
                fh[al * FS2 + kp] = packbf(s0, s1);
                fl[al * FS2 + kp] = packlo(s0, s1);
            }
        } else {
            for (int kp = lane; kp < KP2; kp += 32) {
                float s0 = 0.f, s1 = 0.f;
                if (a >= 0) {
                    #pragma unroll
                    for (int h = 0; h < 2; h++) {
                        int k = 2 * kp + h;
                        float v = 0.f;
                        if (k < INF) {
                            v = xr[k];
                            #pragma unroll
                            for (int d = 0; d < DG; d++)
                                if (nb[d] >= 0) v += X[(size_t)(rowbase + nb[d]) * INF + k];
                        } else if (k < INF + BF) {
                            const float* bp = bonds + (size_t)aa * (DG * BF) + (k - INF);
                            v = bp[0] + bp[6] + bp[12] + bp[18] + bp[24] + bp[30];
                        }
                        if (h == 0) s0 = v; else s1 = v;
                    }
                }
                fh[al * FS2 + kp] = packbf(s0, s1);
                fl[al * FS2 + kp] = packlo(s0, s1);
            }
        }
    }
    __syncthreads();

    // ---- GEMM: warp w -> ch n0..n0+15; A via ldmatrix, B via uint4 LDG.128 ----
    int n0 = w * 16;
    float acc4[4][2][4];
    #pragma unroll
    for (int m = 0; m < 4; m++)
        #pragma unroll
        for (int j = 0; j < 2; j++)
            #pragma unroll
            for (int q = 0; q < 4; q++) acc4[m][j][q] = 0.f;

    const uint4* wb = WB + (size_t)deg * NCH * 512 + w * 64 + lane;

    uint32_t ah_base = smem_u32(fh) + 4 * ((lane & 15) * FS2 + (lane >> 4) * 4);
    uint32_t al_base = smem_u32(fl) + 4 * ((lane & 15) * FS2 + (lane >> 4) * 4);

    #pragma unroll
    for (int c = 0; c < NCH; c++) {
        uint32_t Ah[4][4], Al[4][4];
        #pragma unroll
        for (int m = 0; m < 4; m++) {
            uint32_t off = 4 * (m * 16 * FS2 + c * 8);
            LDSM_X4(Ah[m], ah_base + off);
            LDSM_X4(Al[m], al_base + off);
        }
        uint4 b0 = wb[c * 512];
        uint4 b1 = wb[c * 512 + 32];
        uint32_t Bh[2][2] = {{b0.x, b0.y}, {b1.x, b1.y}};
        uint32_t Bl[2][2] = {{b0.z, b0.w}, {b1.z, b1.w}};

        #pragma unroll
        for (int m = 0; m < 4; m++)
            #pragma unroll
            for (int j = 0; j < 2; j++) {
                mma16816(acc4[m][j], Ah[m], Bh[j]);
                mma16816(acc4[m][j], Al[m], Bh[j]);
                mma16816(acc4[m][j], Ah[m], Bl[j]);
            }
    }

    // ---- epilogue: bias + relu, direct float2 stores ----
    float2 b2[2];
    #pragma unroll
    for (int j = 0; j < 2; j++) {
        int ch = n0 + j * 8 + 2 * tr;
        b2[j] = make_float2(bias[deg * HID + ch], bias[deg * HID + ch + 1]);
    }
    #pragma unroll
    for (int m = 0; m < 4; m++) {
        int a0 = satom[m * 16 + tq];
        int a1 = satom[m * 16 + tq + 8];
        #pragma unroll
        for (int j = 0; j < 2; j++) {
            int ch = n0 + j * 8 + 2 * tr;
            if (a0 >= 0)
                *reinterpret_cast<float2*>(&g_x1[(size_t)a0 * HID + ch]) =
                    make_float2(fmaxf(acc4[m][j][0] + b2[j].x, 0.f),
                                fmaxf(acc4[m][j][1] + b2[j].y, 0.f));
            if (a1 >= 0)
                *reinterpret_cast<float2*>(&g_x1[(size_t)a1 * HID + ch]) =
                    make_float2(fmaxf(acc4[m][j][2] + b2[j].x, 0.f),
                                fmaxf(acc4[m][j][3] + b2[j].y, 0.f));
        }
    }
}

// ============================ pool ============================
__global__ __launch_bounds__(256)
void pool_kernel(const int* __restrict__ edges) {
    int w = threadIdx.x >> 5, lane = threadIdx.x & 31;
    int a = blockIdx.x * 8 + w;
    int rowbase = (a / NA) * NA;
    int e = (lane < DG) ? edges[a * DG + lane] : -1;
    unsigned ball = __ballot_sync(FULL, e >= 0);
    int nb[DG];
    #pragma unroll
    for (int d = 0; d < DG; d++) nb[d] = __shfl_sync(FULL, e, d);
    int o = lane * 4;
    float4 v = *reinterpret_cast<const float4*>(g_x1 + (size_t)a * HID + o);
    #pragma unroll
    for (int d = 0; d < DG; d++) {
        if (nb[d] >= 0) {
            float4 u = *reinterpret_cast<const float4*>(g_x1 + (size_t)(rowbase + nb[d]) * HID + o);
            v.x = fmaxf(v.x, u.x); v.y = fmaxf(v.y, u.y);
            v.z = fmaxf(v.z, u.z); v.w = fmaxf(v.w, u.w);
        }
    }
    if (ball == 0u) v = make_float4(0.f, 0.f, 0.f, 0.f);
    *reinterpret_cast<float4*>(g_x2 + (size_t)a * HID + o) = v;
}

// ============================ gout (mma.sync) ============================
__global__ __launch_bounds__(256)
void gout_mma_kernel(const int*   __restrict__ edges,
                     const float* __restrict__ bonds,
                     const float* __restrict__ bo,
                     const float* __restrict__ Wfc,
                     const float* __restrict__ bfc,
                     float* __restrict__ out) {
    constexpr int KP2 = 72, NCH = 9, FS2 = 76;
    __shared__ __align__(16) uint32_t fh[64 * FS2];
    __shared__ __align__(16) uint32_t fl[64 * FS2];
    __shared__ float svalid[64];
    __shared__ float sfp[HID];

    int tid = threadIdx.x, w = tid >> 5, lane = tid & 31;
    int tq = lane >> 2, tr = lane & 3;
    int g = blockIdx.x;
    int rowbase = g * NA;

    // ---- stage A: inline pool2 (float4) + bondsum + validity ----
    for (int j = 0; j < 8; j++) {
        int al = w * 8 + j;
        bool ok = (al < NA);
        int a = rowbase + (ok ? al : 0);
        int e = -1;
        if (lane < DG && ok) e = edges[a * DG + lane];
        unsigned ball = __ballot_sync(FULL, e >= 0);
        int nb[DG];
        #pragma unroll
        for (int d = 0; d < DG; d++) nb[d] = __shfl_sync(FULL, e, d);
        bool valid = ok && (ball != 0u);

        float4 v = make_float4(0.f, 0.f, 0.f, 0.f);
        if (valid) {
            v = *reinterpret_cast<const float4*>(g_x1 + (size_t)a * HID + 4 * lane);
            #pragma unroll
            for (int d = 0; d < DG; d++)
                if (nb[d] >= 0) {
                    float4 u = *reinterpret_cast<const float4*>(
                        g_x1 + (size_t)(rowbase + nb[d]) * HID + 4 * lane);
                    v.x = fmaxf(v.x, u.x); v.y = fmaxf(v.y, u.y);
                    v.z = fmaxf(v.z, u.z); v.w = fmaxf(v.w, u.w);
                }
        }
        int kp0 = 2 * lane;
        *reinterpret_cast<uint2*>(&fh[al * FS2 + kp0]) =
            make_uint2(packbf(v.x, v.y), packbf(v.z, v.w));
        *reinterpret_cast<uint2*>(&fl[al * FS2 + kp0]) =
            make_uint2(packlo(v.x, v.y), packlo(v.z, v.w));
        if (lane < 8) {
            int kp = 64 + lane;
            float s0 = 0.f, s1 = 0.f;
            if (valid) {
                int f0 = 2 * lane, f1 = 2 * lane + 1;
                if (f0 < BF) {
                    const float* bp = bonds + (size_t)a * (DG * BF) + f0;
                    s0 = bp[0] + bp[6] + bp[12] + bp[18] + bp[24] + bp[30];
                }
                if (f1 < BF) {
                    const float* bp = bonds + (size_t)a * (DG * BF) + f1;
                    s1 = bp[0] + bp[6] + bp[12] + bp[18] + bp[24] + bp[30];
                }
            }
            fh[al * FS2 + kp] = packbf(s0, s1);
            fl[al * FS2 + kp] = packlo(s0, s1);
        }
        if (lane == 0) svalid[al] = valid ? 1.f : 0.f;
    }
    __syncthreads();

    // ---- GEMM ----
    int n0 = w * 16;
    float acc4[4][2][4];
    #pragma unroll
    for (int m = 0; m < 4; m++)
        #pragma unroll
        for (int j = 0; j < 2; j++)
            #pragma unroll
            for (int q = 0; q < 4; q++) acc4[m][j][q] = 0.f;

    const uint4* wb = g_WBo + w * 64 + lane;

    uint32_t ah_base = smem_u32(fh) + 4 * ((lane & 15) * FS2 + (lane >> 4) * 4);
    uint32_t al_base = smem_u32(fl) + 4 * ((lane & 15) * FS2 + (lane >> 4) * 4);

    #pragma unroll
    for (int c = 0; c < NCH; c++) {
        uint32_t Ah[4][4], Al[4][4];
        #pragma unroll
        for (int m = 0; m < 4; m++) {
            uint32_t off = 4 * (m * 16 * FS2 + c * 8);
            LDSM_X4(Ah[m], ah_base + off);
            LDSM_X4(Al[m], al_base + off);
        }
        uint4 b0 = wb[c * 512];
        uint4 b1 = wb[c * 512 + 32];
        uint32_t Bh[2][2] = {{b0.x, b0.y}, {b1.x, b1.y}};
        uint32_t Bl[2][2] = {{b0.z, b0.w}, {b1.z, b1.w}};

        #pragma unroll
        for (int m = 0; m < 4; m++)
            #pragma unroll
            for (int j = 0; j < 2; j++) {
                mma16816(acc4[m][j], Ah[m], Bh[j]);
                mma16816(acc4[m][j], Al[m], Bh[j]);
                mma16816(acc4[m][j], Ah[m], Bl[j]);
            }
    }

    // ---- epilogue: bias + tanh + mask, reduce over atoms ----
    float2 b2[2];
    #pragma unroll
    for (int j = 0; j < 2; j++) {
        int ch = n0 + j * 8 + 2 * tr;
        b2[j] = make_float2(bo[ch], bo[ch + 1]);
    }
    float cs[2][2] = {{0.f, 0.f}, {0.f, 0.f}};
    #pragma unroll
    for (int m = 0; m < 4; m++) {
        float v0 = svalid[m * 16 + tq];
        float v1 = svalid[m * 16 + tq + 8];
        #pragma unroll
        for (int j = 0; j < 2; j++) {
            cs[j][0] += v0 * htanh(acc4[m][j][0] + b2[j].x)
                      + v1 * htanh(acc4[m][j][2] + b2[j].x);
            cs[j][1] += v0 * htanh(acc4[m][j][1] + b2[j].y)
                      + v1 * htanh(acc4[m][j][3] + b2[j].y);
        }
    }
    #pragma unroll
    for (int off = 4; off < 32; off <<= 1) {
        #pragma unroll
        for (int j = 0; j < 2; j++) {
            cs[j][0] += __shfl_xor_sync(FULL, cs[j][0], off);
            cs[j][1] += __shfl_xor_sync(FULL, cs[j][1], off);
        }
    }
    if (tq == 0) {
        #pragma unroll
        for (int j = 0; j < 2; j++) {
            int ch = n0 + j * 8 + 2 * tr;
            sfp[ch]     = cs[j][0];
            sfp[ch + 1] = cs[j][1];
        }
    }
    __syncthreads();

    if (tid < NC) {
        float v = bfc[tid];
        #pragma unroll 8
        for (int o = 0; o < HID; o++) v = fmaf(sfp[o], Wfc[o * NC + tid], v);
        out[g * NC + tid] = 1.0f / (1.0f + expf(-v));
    }
}

// ---------------------------------------------------------------------------
extern "C" void kernel_launch(void* const* d_in, const int* in_sizes, int n_in,
                              void* d_out, int out_size) {
    const float* atoms = (const float*)d_in[0];
    const float* bonds = (const float*)d_in[1];
    const int*   edges = (const int*)  d_in[2];
    const float* W1    = (const float*)d_in[3];
    const float* b1    = (const float*)d_in[4];
    const float* W2    = (const float*)d_in[5];
    const float* b2    = (const float*)d_in[6];
    const float* Wo    = (const float*)d_in[7];
    const float* bo    = (const float*)d_in[8];
    const float* Wfc   = (const float*)d_in[9];
    const float* bfc   = (const float*)d_in[10];
    float* out = (float*)d_out;

    // launch order chosen so conv1 is the 4th launch (the one ncu samples)
    zero_cnt_kernel<<<1, 32>>>();
    prep_kernel<<<BN / 256, 256>>>(edges);
    wprep_all_kernel<<<(6*3*512 + 6*9*512 + 9*512 + 255) / 256, 256>>>(W1, W2, Wo);

    conv_mma_kernel<AF, 48, 28, 0, true><<<MAXT, 256>>>(atoms, bonds, edges, b1);
    pool_kernel<<<BN / 8, 256>>>(edges);
    conv_mma_kernel<HID, 144, 76, 1, false><<<MAXT, 256>>>(nullptr, bonds, edges, b2);
    gout_mma_kernel<<<B, 256>>>(edges, bonds, bo, Wfc, bfc, out);
}

// round 15
// speedup vs baseline: 1.5610x; 1.0626x over previous
#include <cuda_runtime.h>
#include <cuda_bf16.h>
#include <cstdint>

#define FULL 0xFFFFFFFFu

constexpr int B   = 2048;
constexpr int NA  = 60;
constexpr int DG  = 6;
constexpr int AF  = 37;
constexpr int BF  = 6;
constexpr int HID = 128;
constexpr int NC  = 12;
constexpr int BN  = B * NA;
constexpr int MAXT = 1926;          // max total conv tiles: 122880/64 + 6

// ---- scratch (allocation-free) ----
__device__ float    g_x1[BN * HID];
__device__ float    g_x2[BN * HID];
__device__ int      g_bidx[7 * BN];
__device__ int      g_bcnt[8];
// B-fragment-packed weights: entry (deg,c,w,j,lane) -> uint4{hi@kp0,hi@kp1,lo@kp0,lo@kp1}
__device__ uint4    g_WB1[6 * 3 * 512];
__device__ uint4    g_WB2[6 * 9 * 512];
__device__ uint4    g_WBo[9 * 512];

__device__ __forceinline__ float htanh(float x) {
    float y; asm("tanh.approx.f32 %0, %1;" : "=f"(y) : "f"(x)); return y;
}
__device__ __forceinline__ uint16_t bf16b(float x) {
    return __bfloat16_as_ushort(__float2bfloat16(x));
}
__device__ __forceinline__ uint32_t smem_u32(const void* p) {
    uint32_t a;
    asm("{ .reg .u64 t; cvta.to.shared.u64 t, %1; cvt.u32.u64 %0, t; }" : "=r"(a) : "l"(p));
    return a;
}
__device__ __forceinline__ uint32_t packbf(float s0, float s1) {
    __nv_bfloat16 h0 = __float2bfloat16(s0), h1 = __float2bfloat16(s1);
    return (uint32_t)__bfloat16_as_ushort(h0) | ((uint32_t)__bfloat16_as_ushort(h1) << 16);
}
__device__ __forceinline__ uint32_t packlo(float s0, float s1) {
    __nv_bfloat16 h0 = __float2bfloat16(s0), h1 = __float2bfloat16(s1);
    return (uint32_t)bf16b(s0 - __bfloat162float(h0)) |
           ((uint32_t)bf16b(s1 - __bfloat162float(h1)) << 16);
}
__device__ __forceinline__ void mma16816(float* d, const uint32_t* a, const uint32_t* b) {
    asm volatile("mma.sync.aligned.m16n8k16.row.col.f32.bf16.bf16.f32 "
                 "{%0,%1,%2,%3}, {%4,%5,%6,%7}, {%8,%9}, {%0,%1,%2,%3};"
                 : "+f"(d[0]), "+f"(d[1]), "+f"(d[2]), "+f"(d[3])
                 : "r"(a[0]), "r"(a[1]), "r"(a[2]), "r"(a[3]), "r"(b[0]), "r"(b[1]));
}
#define LDSM_X4(r, a) \
    asm volatile("ldmatrix.sync.aligned.m8n8.x4.shared.b16 {%0,%1,%2,%3}, [%4];" \
                 : "=r"((r)[0]), "=r"((r)[1]), "=r"((r)[2]), "=r"((r)[3]) : "r"(a))

// ============================ prep ============================
__global__ void zero_cnt_kernel() { if (threadIdx.x < 8) g_bcnt[threadIdx.x] = 0; }

__global__ __launch_bounds__(256)
void prep_kernel(const int* __restrict__ edges) {
    int a = blockIdx.x * blockDim.x + threadIdx.x;
    if (a >= BN) return;
    int deg = 0;
    #pragma unroll
    for (int d = 0; d < DG; d++) deg += (edges[a * DG + d] >= 0);
    int pos = atomicAdd(&g_bcnt[deg], 1);
    g_bidx[deg * BN + pos] = a;
}

// ==================== weight repack (B-fragment uint4 layout) ====================
__device__ __forceinline__ void wsplit4(const float* __restrict__ W, uint4* dst,
                                        int IN, int NCH, int sub) {
    int lane = sub & 31;
    int j    = (sub >> 5) & 1;
    int w    = (sub >> 6) & 7;
    int rest = sub >> 9;
    int c    = rest % NCH;
    int deg  = rest / NCH;
    int tq = lane >> 2, tr = lane & 3;
    int ch  = w * 16 + j * 8 + tq;
    int kp0 = c * 8 + tr, kp1 = kp0 + 4;

    uint32_t ww[4];
    #pragma unroll
    for (int q = 0; q < 2; q++) {
        int kp = q ? kp1 : kp0;
        int k0 = 2 * kp, k1 = 2 * kp + 1;
        float w0 = (k0 < IN) ? W[(deg * IN + k0) * HID + ch] : 0.f;
        float w1 = (k1 < IN) ? W[(deg * IN + k1) * HID + ch] : 0.f;
        __nv_bfloat16 h0 = __float2bfloat16(w0), h1 = __float2bfloat16(w1);
        ww[q]     = (uint32_t)__bfloat16_as_ushort(h0) |
                    ((uint32_t)__bfloat16_as_ushort(h1) << 16);
        ww[2 + q] = (uint32_t)bf16b(w0 - __bfloat162float(h0)) |
                    ((uint32_t)bf16b(w1 - __bfloat162float(h1)) << 16);
    }
    dst[sub] = make_uint4(ww[0], ww[1], ww[2], ww[3]);
}

__global__ __launch_bounds__(256)
void wprep_all_kernel(const float* __restrict__ W1, const float* __restrict__ W2,
                      const float* __restrict__ Wo) {
    constexpr int E1 = 6 * 3 * 512, E2 = 6 * 9 * 512, Eo = 9 * 512;
    int idx = blockIdx.x * blockDim.x + threadIdx.x;
    if (idx < E1)                wsplit4(W1, g_WB1, 43, 3, idx);
    else if (idx < E1 + E2)      wsplit4(W2, g_WB2, 134, 9, idx - E1);
    else if (idx < E1 + E2 + Eo) wsplit4(Wo, g_WBo, 134, 9, idx - E1 - E2);
}

// ============================ conv (mma.sync) ============================
template <int INF, int KUSED, int FS2, int WSEL, bool USE_EXT>
__global__ __launch_bounds__(256)
void conv_mma_kernel(const float* __restrict__ Xext,
                     const float* __restrict__ bonds,
                     const int*   __restrict__ edges,
                     const float* __restrict__ bias) {
    constexpr int KP2 = KUSED / 2;
    constexpr int NCH = KUSED / 16;
    __shared__ __align__(16) uint32_t fh[64 * FS2];
    __shared__ __align__(16) uint32_t fl[64 * FS2];
    __shared__ int satom[64];

    const float* __restrict__ X = USE_EXT ? Xext : (const float*)g_x2;
    const uint4* __restrict__ WB = (WSEL == 0) ? g_WB1 : g_WB2;

    // in-register tile prefix over g_bcnt
    int bid = blockIdx.x;
    int deg = 0, tb = 0, acc = 0;
    #pragma unroll
    for (int d = 0; d < 7; d++) {
        int nt = (g_bcnt[d] + 63) >> 6;
        if (bid >= acc && bid < acc + nt) { deg = d; tb = acc; }
        acc += nt;
    }
    if (bid >= acc) return;
    int cnt = g_bcnt[deg];
    int t0  = (bid - tb) * 64;

    int tid = threadIdx.x, w = tid >> 5, lane = tid & 31;
    int tq = lane >> 2, tr = lane & 3;

    if (tid < 64) {
        int i = t0 + tid;
        satom[tid] = (i < cnt) ? g_bidx[deg * BN + i] : -1;
    }
    __syncthreads();

    if (deg >= DG) {      // deg==6 bucket (empty in practice): zero outputs
        for (int idx = tid; idx < 64 * 32; idx += 256) {
            int al = idx >> 5, q = idx & 31;
            int a = satom[al];
            if (a >= 0)
                *reinterpret_cast<float4*>(&g_x1[(size_t)a * HID + q * 4]) =
                    make_float4(0.f, 0.f, 0.f, 0.f);
        }
        return;
    }

    // ---- edge prefetch: all 48 edges of this warp's 8 atoms in 2 LDGs ----
    int e0 = -1, e1 = -1;
    {
        int f0 = lane;                    // flat = j*6 + d, f0 in [0,32)
        int a0 = satom[w * 8 + f0 / 6];
        if (a0 >= 0) e0 = edges[a0 * DG + f0 % 6];
        if (lane < 16) {
            int f1 = 32 + lane;           // [32,48)
            int a1 = satom[w * 8 + f1 / 6];
            if (a1 >= 0) e1 = edges[a1 * DG + f1 % 6];
        }
    }

    // ---- stage A: warp w handles atoms w*8 .. w*8+7 (all rounds in flight) ----
    #pragma unroll
    for (int j = 0; j < 8; j++) {
        int al = w * 8 + j;
        int a  = satom[al];
        int aa = (a >= 0) ? a : 0;
        int nb[DG];
        #pragma unroll
        for (int d = 0; d < DG; d++) {
            int f = j * 6 + d;
            nb[d] = (f < 32) ? __shfl_sync(FULL, e0, f) : __shfl_sync(FULL, e1, f - 32);
        }
        int rowbase = (aa / NA) * NA;
        const float* xr = X + (size_t)aa * INF;

        if constexpr (INF == HID) {
            float4 v = make_float4(0.f, 0.f, 0.f, 0.f);
            if (a >= 0) {
                v = *reinterpret_cast<const float4*>(xr + 4 * lane);
                #pragma unroll
                for (int d = 0; d < DG; d++)
                    if (nb[d] >= 0) {
                        float4 u = *reinterpret_cast<const float4*>(
                            X + (size_t)(rowbase + nb[d]) * HID + 4 * lane);
                        v.x += u.x; v.y += u.y; v.z += u.z; v.w += u.w;
                    }
            }
            int kp0 = 2 * lane;
            *reinterpret_cast<uint2*>(&fh[al * FS2 + kp0]) =
                make_uint2(packbf(v.x, v.y), packbf(v.z, v.w));
            *reinterpret_cast<uint2*>(&fl[al * FS2 + kp0]) =
                make_uint2(packlo(v.x, v.y), packlo(v.z, v.w));
            if (lane < 8) {
                int kp = 64 + lane;
                float s0 = 0.f, s1 = 0.f;
                if (a >= 0) {
                    int f0 = 2 * lane, f1 = 2 * lane + 1;   // bond features
                    if (f0 < BF) {
                        const float* bp = bonds + (size_t)aa * (DG * BF) + f0;
                        s0 = bp[0] + bp[6] + bp[12] + bp[18] + bp[24] + bp[30];
                    }
                    if (f1 < BF) {
                        const float* bp = bonds + (size_t)aa * (DG * BF) + f1;
                        s1 = bp[0] + bp[6] + bp[12] + bp[18] + bp[24] + bp[30];
                    }
                }
                fh[al * FS2 + kp] = packbf(s0, s1);
                fl[al * FS2 + kp] = packlo(s0, s1);
            }
        } else {
            for (int kp = lane; kp < KP2; kp += 32) {
                float s0 = 0.f, s1 = 0.f;
                if (a >= 0) {
                    #pragma unroll
                    for (int h = 0; h < 2; h++) {
                        int k = 2 * kp + h;
                        float v = 0.f;
                        if (k < INF) {
                            v = xr[k];
                            #pragma unroll
                            for (int d = 0; d < DG; d++)
                                if (nb[d] >= 0) v += X[(size_t)(rowbase + nb[d]) * INF + k];
                        } else if (k < INF + BF) {
                            const float* bp = bonds + (size_t)aa * (DG * BF) + (k - INF);
                            v = bp[0] + bp[6] + bp[12] + bp[18] + bp[24] + bp[30];
                        }
                        if (h == 0) s0 = v; else s1 = v;
                    }
                }
                fh[al * FS2 + kp] = packbf(s0, s1);
                fl[al * FS2 + kp] = packlo(s0, s1);
            }
        }
    }
    __syncthreads();

    // ---- GEMM: warp w -> ch n0..n0+15; A via ldmatrix, B via uint4 LDG.128 ----
    int n0 = w * 16;
    float acc4[4][2][4];
    #pragma unroll
    for (int m = 0; m < 4; m++)
        #pragma unroll
        for (int j = 0; j < 2; j++)
            #pragma unroll
            for (int q = 0; q < 4; q++) acc4[m][j][q] = 0.f;

    const uint4* wb = WB + (size_t)deg * NCH * 512 + w * 64 + lane;

    uint32_t ah_base = smem_u32(fh) + 4 * ((lane & 15) * FS2 + (lane >> 4) * 4);
    uint32_t al_base = smem_u32(fl) + 4 * ((lane & 15) * FS2 + (lane >> 4) * 4);

    #pragma unroll
    for (int c = 0; c < NCH; c++) {
        uint32_t Ah[4][4], Al[4][4];
        #pragma unroll
        for (int m = 0; m < 4; m++) {
            uint32_t off = 4 * (m * 16 * FS2 + c * 8);
            LDSM_X4(Ah[m], ah_base + off);
            LDSM_X4(Al[m], al_base + off);
        }
        uint4 b0 = wb[c * 512];
        uint4 b1 = wb[c * 512 + 32];
        uint32_t Bh[2][2] = {{b0.x, b0.y}, {b1.x, b1.y}};
        uint32_t Bl[2][2] = {{b0.z, b0.w}, {b1.z, b1.w}};

        #pragma unroll
        for (int m = 0; m < 4; m++)
            #pragma unroll
            for (int j = 0; j < 2; j++) {
                mma16816(acc4[m][j], Ah[m], Bh[j]);
                mma16816(acc4[m][j], Al[m], Bh[j]);
                mma16816(acc4[m][j], Ah[m], Bl[j]);
            }
    }

    // ---- epilogue: bias + relu, direct float2 stores ----
    float2 b2[2];
    #pragma unroll
    for (int j = 0; j < 2; j++) {
        int ch = n0 + j * 8 + 2 * tr;
        b2[j] = make_float2(bias[deg * HID + ch], bias[deg * HID + ch + 1]);
    }
    #pragma unroll
    for (int m = 0; m < 4; m++) {
        int a0 = satom[m * 16 + tq];
        int a1 = satom[m * 16 + tq + 8];
        #pragma unroll
        for (int j = 0; j < 2; j++) {
            int ch = n0 + j * 8 + 2 * tr;
            if (a0 >= 0)
                *reinterpret_cast<float2*>(&g_x1[(size_t)a0 * HID + ch]) =
                    make_float2(fmaxf(acc4[m][j][0] + b2[j].x, 0.f),
                                fmaxf(acc4[m][j][1] + b2[j].y, 0.f));
            if (a1 >= 0)
                *reinterpret_cast<float2*>(&g_x1[(size_t)a1 * HID + ch]) =
                    make_float2(fmaxf(acc4[m][j][2] + b2[j].x, 0.f),
                                fmaxf(acc4[m][j][3] + b2[j].y, 0.f));
        }
    }
}

// ============================ pool ============================
__global__ __launch_bounds__(256)
void pool_kernel(const int* __restrict__ edges) {
    int w = threadIdx.x >> 5, lane = threadIdx.x & 31;
    int a = blockIdx.x * 8 + w;
    int rowbase = (a / NA) * NA;
    int e = (lane < DG) ? edges[a * DG + lane] : -1;
    unsigned ball = __ballot_sync(FULL, e >= 0);
    int nb[DG];
    #pragma unroll
    for (int d = 0; d < DG; d++) nb[d] = __shfl_sync(FULL, e, d);
    int o = lane * 4;
    float4 v = *reinterpret_cast<const float4*>(g_x1 + (size_t)a * HID + o);
    #pragma unroll
    for (int d = 0; d < DG; d++) {
        if (nb[d] >= 0) {
            float4 u = *reinterpret_cast<const float4*>(g_x1 + (size_t)(rowbase + nb[d]) * HID + o);
            v.x = fmaxf(v.x, u.x); v.y = fmaxf(v.y, u.y);
            v.z = fmaxf(v.z, u.z); v.w = fmaxf(v.w, u.w);
        }
    }
    if (ball == 0u) v = make_float4(0.f, 0.f, 0.f, 0.f);
    *reinterpret_cast<float4*>(g_x2 + (size_t)a * HID + o) = v;
}

// ============================ gout (mma.sync) ============================
__global__ __launch_bounds__(256)
void gout_mma_kernel(const int*   __restrict__ edges,
                     const float* __restrict__ bonds,
                     const float* __restrict__ bo,
                     const float* __restrict__ Wfc,
                     const float* __restrict__ bfc,
                     float* __restrict__ out) {
    constexpr int KP2 = 72, NCH = 9, FS2 = 76;
    __shared__ __align__(16) uint32_t fh[64 * FS2];
    __shared__ __align__(16) uint32_t fl[64 * FS2];
    __shared__ float svalid[64];
    __shared__ float sfp[HID];

    int tid = threadIdx.x, w = tid >> 5, lane = tid & 31;
    int tq = lane >> 2, tr = lane & 3;
    int g = blockIdx.x;
    int rowbase = g * NA;

    // ---- edge prefetch for this warp's 8 atom slots ----
    int e0 = -1, e1 = -1;
    {
        int f0 = lane;
        int al0 = w * 8 + f0 / 6;
        if (al0 < NA) e0 = edges[(rowbase + al0) * DG + f0 % 6];
        if (lane < 16) {
            int f1 = 32 + lane;
            int al1 = w * 8 + f1 / 6;
            if (al1 < NA) e1 = edges[(rowbase + al1) * DG + f1 % 6];
        }
    }

    // ---- stage A: inline pool2 (float4) + bondsum + validity ----
    #pragma unroll
    for (int j = 0; j < 8; j++) {
        int al = w * 8 + j;
        bool ok = (al < NA);
        int a = rowbase + (ok ? al : 0);
        int nb[DG];
        #pragma unroll
        for (int d = 0; d < DG; d++) {
            int f = j * 6 + d;
            nb[d] = (f < 32) ? __shfl_sync(FULL, e0, f) : __shfl_sync(FULL, e1, f - 32);
        }
        bool anyn = (nb[0] >= 0) | (nb[1] >= 0) | (nb[2] >= 0) |
                    (nb[3] >= 0) | (nb[4] >= 0) | (nb[5] >= 0);
        bool valid = ok && anyn;

        float4 v = make_float4(0.f, 0.f, 0.f, 0.f);
        if (valid) {
            v = *reinterpret_cast<const float4*>(g_x1 + (size_t)a * HID + 4 * lane);
            #pragma unroll
            for (int d = 0; d < DG; d++)
                if (nb[d] >= 0) {
                    float4 u = *reinterpret_cast<const float4*>(
                        g_x1 + (size_t)(rowbase + nb[d]) * HID + 4 * lane);
                    v.x = fmaxf(v.x, u.x); v.y = fmaxf(v.y, u.y);
                    v.z = fmaxf(v.z, u.z); v.w = fmaxf(v.w, u.w);
                }
        }
        int kp0 = 2 * lane;
        *reinterpret_cast<uint2*>(&fh[al * FS2 + kp0]) =
            make_uint2(packbf(v.x, v.y), packbf(v.z, v.w));
        *reinterpret_cast<uint2*>(&fl[al * FS2 + kp0]) =
            make_uint2(packlo(v.x, v.y), packlo(v.z, v.w));
        if (lane < 8) {
            int kp = 64 + lane;
            float s0 = 0.f, s1 = 0.f;
            if (valid) {
                int f0 = 2 * lane, f1 = 2 * lane + 1;
                if (f0 < BF) {
                    const float* bp = bonds + (size_t)a * (DG * BF) + f0;
                    s0 = bp[0] + bp[6] + bp[12] + bp[18] + bp[24] + bp[30];
                }
                if (f1 < BF) {
                    const float* bp = bonds + (size_t)a * (DG * BF) + f1;
                    s1 = bp[0] + bp[6] + bp[12] + bp[18] + bp[24] + bp[30];
                }
            }
            fh[al * FS2 + kp] = packbf(s0, s1);
            fl[al * FS2 + kp] = packlo(s0, s1);
        }
        if (lane == 0) svalid[al] = valid ? 1.f : 0.f;
    }
    __syncthreads();

    // ---- GEMM ----
    int n0 = w * 16;
    float acc4[4][2][4];
    #pragma unroll
    for (int m = 0; m < 4; m++)
        #pragma unroll
        for (int j = 0; j < 2; j++)
            #pragma unroll
            for (int q = 0; q < 4; q++) acc4[m][j][q] = 0.f;

    const uint4* wb = g_WBo + w * 64 + lane;

    uint32_t ah_base = smem_u32(fh) + 4 * ((lane & 15) * FS2 + (lane >> 4) * 4);
    uint32_t al_base = smem_u32(fl) + 4 * ((lane & 15) * FS2 + (lane >> 4) * 4);

    #pragma unroll
    for (int c = 0; c < NCH; c++) {
        uint32_t Ah[4][4], Al[4][4];
        #pragma unroll
        for (int m = 0; m < 4; m++) {
            uint32_t off = 4 * (m * 16 * FS2 + c * 8);
            LDSM_X4(Ah[m], ah_base + off);
            LDSM_X4(Al[m], al_base + off);
        }
        uint4 b0 = wb[c * 512];
        uint4 b1 = wb[c * 512 + 32];
        uint32_t Bh[2][2] = {{b0.x, b0.y}, {b1.x, b1.y}};
        uint32_t Bl[2][2] = {{b0.z, b0.w}, {b1.z, b1.w}};

        #pragma unroll
        for (int m = 0; m < 4; m++)
            #pragma unroll
            for (int j = 0; j < 2; j++) {
                mma16816(acc4[m][j], Ah[m], Bh[j]);
                mma16816(acc4[m][j], Al[m], Bh[j]);
                mma16816(acc4[m][j], Ah[m], Bl[j]);
            }
    }

    // ---- epilogue: bias + tanh + mask, reduce over atoms ----
    float2 b2[2];
    #pragma unroll
    for (int j = 0; j < 2; j++) {
        int ch = n0 + j * 8 + 2 * tr;
        b2[j] = make_float2(bo[ch], bo[ch + 1]);
    }
    float cs[2][2] = {{0.f, 0.f}, {0.f, 0.f}};
    #pragma unroll
    for (int m = 0; m < 4; m++) {
        float v0 = svalid[m * 16 + tq];
        float v1 = svalid[m * 16 + tq + 8];
        #pragma unroll
        for (int j = 0; j < 2; j++) {
            cs[j][0] += v0 * htanh(acc4[m][j][0] + b2[j].x)
                      + v1 * htanh(acc4[m][j][2] + b2[j].x);
            cs[j][1] += v0 * htanh(acc4[m][j][1] + b2[j].y)
                      + v1 * htanh(acc4[m][j][3] + b2[j].y);
        }
    }
    #pragma unroll
    for (int off = 4; off < 32; off <<= 1) {
        #pragma unroll
        for (int j = 0; j < 2; j++) {
            cs[j][0] += __shfl_xor_sync(FULL, cs[j][0], off);
            cs[j][1] += __shfl_xor_sync(FULL, cs[j][1], off);
        }
    }
    if (tq == 0) {
        #pragma unroll
        for (int j = 0; j < 2; j++) {
            int ch = n0 + j * 8 + 2 * tr;
            sfp[ch]     = cs[j][0];
            sfp[ch + 1] = cs[j][1];
        }
    }
    __syncthreads();

    if (tid < NC) {
        float v = bfc[tid];
        #pragma unroll 8
        for (int o = 0; o < HID; o++) v = fmaf(sfp[o], Wfc[o * NC + tid], v);
        out[g * NC + tid] = 1.0f / (1.0f + expf(-v));
    }
}

// ---------------------------------------------------------------------------
extern "C" void kernel_launch(void* const* d_in, const int* in_sizes, int n_in,
                              void* d_out, int out_size) {
    const float* atoms = (const float*)d_in[0];
    const float* bonds = (const float*)d_in[1];
    const int*   edges = (const int*)  d_in[2];
    const float* W1    = (const float*)d_in[3];
    const float* b1    = (const float*)d_in[4];
    const float* W2    = (const float*)d_in[5];
    const float* b2    = (const float*)d_in[6];
    const float* Wo    = (const float*)d_in[7];
    const float* bo    = (const float*)d_in[8];
    const float* Wfc   = (const float*)d_in[9];
    const float* bfc   = (const float*)d_in[10];
    float* out = (float*)d_out;

    // launch order keeps conv1 as the 4th launch (the one ncu samples)
    zero_cnt_kernel<<<1, 32>>>();
    prep_kernel<<<BN / 256, 256>>>(edges);
    wprep_all_kernel<<<(6*3*512 + 6*9*512 + 9*512 + 255) / 256, 256>>>(W1, W2, Wo);

    conv_mma_kernel<AF, 48, 28, 0, true><<<MAXT, 256>>>(atoms, bonds, edges, b1);
    pool_kernel<<<BN / 8, 256>>>(edges);
    conv_mma_kernel<HID, 144, 76, 1, false><<<MAXT, 256>>>(nullptr, bonds, edges, b2);
    gout_mma_kernel<<<B, 256>>>(edges, bonds, bo, Wfc, bfc, out);
}

// round 16
// speedup vs baseline: 1.7266x; 1.1061x over previous
#include <cuda_runtime.h>
#include <cuda_bf16.h>
#include <cstdint>

#define FULL 0xFFFFFFFFu

constexpr int B   = 2048;
constexpr int NA  = 60;
constexpr int DG  = 6;
constexpr int AF  = 37;
constexpr int BF  = 6;
constexpr int HID = 128;
constexpr int NC  = 12;
constexpr int BN  = B * NA;
constexpr int MAXT = 1926;          // max total conv tiles: 122880/64 + 6

// ---- scratch (allocation-free) ----
__device__ float    g_x1[BN * HID];
__device__ float    g_x2[BN * HID];
__device__ int      g_bidx[7 * BN];
__device__ int      g_bcnt[8];
// B-fragment-packed weights: entry (deg,c,w,j,lane) -> uint4{hi@kp0,hi@kp1,lo@kp0,lo@kp1}
__device__ uint4    g_WB1[6 * 3 * 512];
__device__ uint4    g_WB2[6 * 9 * 512];
__device__ uint4    g_WBo[9 * 512];

__device__ __forceinline__ float htanh(float x) {
    float y; asm("tanh.approx.f32 %0, %1;" : "=f"(y) : "f"(x)); return y;
}
__device__ __forceinline__ uint16_t bf16b(float x) {
    return __bfloat16_as_ushort(__float2bfloat16(x));
}
__device__ __forceinline__ uint32_t smem_u32(const void* p) {
    uint32_t a;
    asm("{ .reg .u64 t; cvta.to.shared.u64 t, %1; cvt.u32.u64 %0, t; }" : "=r"(a) : "l"(p));
    return a;
}
__device__ __forceinline__ uint32_t packbf(float s0, float s1) {
    __nv_bfloat16 h0 = __float2bfloat16(s0), h1 = __float2bfloat16(s1);
    return (uint32_t)__bfloat16_as_ushort(h0) | ((uint32_t)__bfloat16_as_ushort(h1) << 16);
}
__device__ __forceinline__ uint32_t packlo(float s0, float s1) {
    __nv_bfloat16 h0 = __float2bfloat16(s0), h1 = __float2bfloat16(s1);
    return (uint32_t)bf16b(s0 - __bfloat162float(h0)) |
           ((uint32_t)bf16b(s1 - __bfloat162float(h1)) << 16);
}
__device__ __forceinline__ void mma16816(float* d, const uint32_t* a, const uint32_t* b) {
    asm volatile("mma.sync.aligned.m16n8k16.row.col.f32.bf16.bf16.f32 "
                 "{%0,%1,%2,%3}, {%4,%5,%6,%7}, {%8,%9}, {%0,%1,%2,%3};"
                 : "+f"(d[0]), "+f"(d[1]), "+f"(d[2]), "+f"(d[3])
                 : "r"(a[0]), "r"(a[1]), "r"(a[2]), "r"(a[3]), "r"(b[0]), "r"(b[1]));
}
#define LDSM_X4(r, a) \
    asm volatile("ldmatrix.sync.aligned.m8n8.x4.shared.b16 {%0,%1,%2,%3}, [%4];" \
                 : "=r"((r)[0]), "=r"((r)[1]), "=r"((r)[2]), "=r"((r)[3]) : "r"(a))

// ============================ prep ============================
__global__ void zero_cnt_kernel() { if (threadIdx.x < 8) g_bcnt[threadIdx.x] = 0; }

__global__ __launch_bounds__(256)
void prep_kernel(const int* __restrict__ edges) {
    int a = blockIdx.x * blockDim.x + threadIdx.x;
    if (a >= BN) return;
    int deg = 0;
    #pragma unroll
    for (int d = 0; d < DG; d++) deg += (edges[a * DG + d] >= 0);
    int pos = atomicAdd(&g_bcnt[deg], 1);
    g_bidx[deg * BN + pos] = a;
}

// ==================== weight repack (B-fragment uint4 layout) ====================
__device__ __forceinline__ void wsplit4(const float* __restrict__ W, uint4* dst,
                                        int IN, int NCH, int sub) {
    int lane = sub & 31;
    int j    = (sub >> 5) & 1;
    int w    = (sub >> 6) & 7;
    int rest = sub >> 9;
    int c    = rest % NCH;
    int deg  = rest / NCH;
    int tq = lane >> 2, tr = lane & 3;
    int ch  = w * 16 + j * 8 + tq;
    int kp0 = c * 8 + tr, kp1 = kp0 + 4;

    uint32_t ww[4];
    #pragma unroll
    for (int q = 0; q < 2; q++) {
        int kp = q ? kp1 : kp0;
        int k0 = 2 * kp, k1 = 2 * kp + 1;
        float w0 = (k0 < IN) ? W[(deg * IN + k0) * HID + ch] : 0.f;
        float w1 = (k1 < IN) ? W[(deg * IN + k1) * HID + ch] : 0.f;
        __nv_bfloat16 h0 = __float2bfloat16(w0), h1 = __float2bfloat16(w1);
        ww[q]     = (uint32_t)__bfloat16_as_ushort(h0) |
                    ((uint32_t)__bfloat16_as_ushort(h1) << 16);
        ww[2 + q] = (uint32_t)bf16b(w0 - __bfloat162float(h0)) |
                    ((uint32_t)bf16b(w1 - __bfloat162float(h1)) << 16);
    }
    dst[sub] = make_uint4(ww[0], ww[1], ww[2], ww[3]);
}

__global__ __launch_bounds__(256)
void wprep_all_kernel(const float* __restrict__ W1, const float* __restrict__ W2,
                      const float* __restrict__ Wo) {
    constexpr int E1 = 6 * 3 * 512, E2 = 6 * 9 * 512, Eo = 9 * 512;
    int idx = blockIdx.x * blockDim.x + threadIdx.x;
    if (idx < E1)                wsplit4(W1, g_WB1, 43, 3, idx);
    else if (idx < E1 + E2)      wsplit4(W2, g_WB2, 134, 9, idx - E1);
    else if (idx < E1 + E2 + Eo) wsplit4(Wo, g_WBo, 134, 9, idx - E1 - E2);
}

// ============================ conv (mma.sync, 512 threads) ============================
// 16 warps: warp = (m-half mh 0..1) x (n-group ng 0..7). Each warp: 16 ch x 32 atoms
// (2 m-tiles x 2 n-tiles). Staging: each warp stages 4 atoms.
template <int INF, int KUSED, int FS2, int WSEL, bool USE_EXT>
__global__ __launch_bounds__(512, 2)
void conv_mma_kernel(const float* __restrict__ Xext,
                     const float* __restrict__ bonds,
                     const int*   __restrict__ edges,
                     const float* __restrict__ bias) {
    constexpr int KP2 = KUSED / 2;
    constexpr int NCH = KUSED / 16;
    __shared__ __align__(16) uint32_t fh[64 * FS2];
    __shared__ __align__(16) uint32_t fl[64 * FS2];
    __shared__ int satom[64];

    const float* __restrict__ X = USE_EXT ? Xext : (const float*)g_x2;
    const uint4* __restrict__ WB = (WSEL == 0) ? g_WB1 : g_WB2;

    // in-register tile prefix over g_bcnt
    int bid = blockIdx.x;
    int deg = 0, tb = 0, acc = 0;
    #pragma unroll
    for (int d = 0; d < 7; d++) {
        int nt = (g_bcnt[d] + 63) >> 6;
        if (bid >= acc && bid < acc + nt) { deg = d; tb = acc; }
        acc += nt;
    }
    if (bid >= acc) return;
    int cnt = g_bcnt[deg];
    int t0  = (bid - tb) * 64;

    int tid = threadIdx.x, w16 = tid >> 5, lane = tid & 31;
    int ng = w16 & 7, mh = w16 >> 3;
    int tq = lane >> 2, tr = lane & 3;

    if (tid < 64) {
        int i = t0 + tid;
        satom[tid] = (i < cnt) ? g_bidx[deg * BN + i] : -1;
    }
    __syncthreads();

    if (deg >= DG) {      // deg==6 bucket (empty in practice): zero outputs
        for (int idx = tid; idx < 64 * 32; idx += 512) {
            int al = idx >> 5, q = idx & 31;
            int a = satom[al];
            if (a >= 0)
                *reinterpret_cast<float4*>(&g_x1[(size_t)a * HID + q * 4]) =
                    make_float4(0.f, 0.f, 0.f, 0.f);
        }
        return;
    }

    // ---- edge prefetch: 24 edges (4 atoms x 6) in one LDG ----
    int e0 = -1;
    if (lane < 24) {
        int a0 = satom[w16 * 4 + lane / 6];
        if (a0 >= 0) e0 = edges[a0 * DG + lane % 6];
    }

    // ---- stage A: warp w16 stages atoms w16*4 .. +3 ----
    #pragma unroll
    for (int j = 0; j < 4; j++) {
        int al = w16 * 4 + j;
        int a  = satom[al];
        int aa = (a >= 0) ? a : 0;
        int nb[DG];
        #pragma unroll
        for (int d = 0; d < DG; d++) nb[d] = __shfl_sync(FULL, e0, j * 6 + d);
        int rowbase = (aa / NA) * NA;
        const float* xr = X + (size_t)aa * INF;

        if constexpr (INF == HID) {
            float4 v = make_float4(0.f, 0.f, 0.f, 0.f);
            if (a >= 0) {
                v = *reinterpret_cast<const float4*>(xr + 4 * lane);
                #pragma unroll
                for (int d = 0; d < DG; d++)
                    if (nb[d] >= 0) {
                        float4 u = *reinterpret_cast<const float4*>(
                            X + (size_t)(rowbase + nb[d]) * HID + 4 * lane);
                        v.x += u.x; v.y += u.y; v.z += u.z; v.w += u.w;
                    }
            }
            int kp0 = 2 * lane;
            *reinterpret_cast<uint2*>(&fh[al * FS2 + kp0]) =
                make_uint2(packbf(v.x, v.y), packbf(v.z, v.w));
            *reinterpret_cast<uint2*>(&fl[al * FS2 + kp0]) =
                make_uint2(packlo(v.x, v.y), packlo(v.z, v.w));
            if (lane < 8) {
                int kp = 64 + lane;
                float s0 = 0.f, s1 = 0.f;
                if (a >= 0) {
                    int f0 = 2 * lane, f1 = 2 * lane + 1;   // bond features
                    if (f0 < BF) {
                        const float* bp = bonds + (size_t)aa * (DG * BF) + f0;
                        s0 = bp[0] + bp[6] + bp[12] + bp[18] + bp[24] + bp[30];
                    }
                    if (f1 < BF) {
                        const float* bp = bonds + (size_t)aa * (DG * BF) + f1;
                        s1 = bp[0] + bp[6] + bp[12] + bp[18] + bp[24] + bp[30];
                    }
                }
                fh[al * FS2 + kp] = packbf(s0, s1);
                fl[al * FS2 + kp] = packlo(s0, s1);
            }
        } else {
            for (int kp = lane; kp < KP2; kp += 32) {
                float s0 = 0.f, s1 = 0.f;
                if (a >= 0) {
                    #pragma unroll
                    for (int h = 0; h < 2; h++) {
                        int k = 2 * kp + h;
                        float v = 0.f;
                        if (k < INF) {
                            v = xr[k];
                            #pragma unroll
                            for (int d = 0; d < DG; d++)
                                if (nb[d] >= 0) v += X[(size_t)(rowbase + nb[d]) * INF + k];
                        } else if (k < INF + BF) {
                            const float* bp = bonds + (size_t)aa * (DG * BF) + (k - INF);
                            v = bp[0] + bp[6] + bp[12] + bp[18] + bp[24] + bp[30];
                        }
                        if (h == 0) s0 = v; else s1 = v;
                    }
                }
                fh[al * FS2 + kp] = packbf(s0, s1);
                fl[al * FS2 + kp] = packlo(s0, s1);
            }
        }
    }
    __syncthreads();

    // ---- GEMM: warp -> 16 ch x 32 atoms (2 m-tiles x 2 n-tiles) ----
    int n0 = ng * 16;
    float acc4[2][2][4];
    #pragma unroll
    for (int m = 0; m < 2; m++)
        #pragma unroll
        for (int j = 0; j < 2; j++)
            #pragma unroll
            for (int q = 0; q < 4; q++) acc4[m][j][q] = 0.f;

    const uint4* wb = WB + (size_t)deg * NCH * 512 + ng * 64 + lane;

    uint32_t ah_base = smem_u32(fh) + 4 * ((mh * 32 + (lane & 15)) * FS2 + (lane >> 4) * 4);
    uint32_t al_base = smem_u32(fl) + 4 * ((mh * 32 + (lane & 15)) * FS2 + (lane >> 4) * 4);

    #pragma unroll
    for (int c = 0; c < NCH; c++) {
        uint32_t Ah[2][4], Al[2][4];
        #pragma unroll
        for (int m = 0; m < 2; m++) {
            uint32_t off = 4 * (m * 16 * FS2 + c * 8);
            LDSM_X4(Ah[m], ah_base + off);
            LDSM_X4(Al[m], al_base + off);
        }
        uint4 b0 = wb[c * 512];
        uint4 b1 = wb[c * 512 + 32];
        uint32_t Bh[2][2] = {{b0.x, b0.y}, {b1.x, b1.y}};
        uint32_t Bl[2][2] = {{b0.z, b0.w}, {b1.z, b1.w}};

        #pragma unroll
        for (int m = 0; m < 2; m++)
            #pragma unroll
            for (int j = 0; j < 2; j++) {
                mma16816(acc4[m][j], Ah[m], Bh[j]);
                mma16816(acc4[m][j], Al[m], Bh[j]);
                mma16816(acc4[m][j], Ah[m], Bl[j]);
            }
    }

    // ---- epilogue: bias + relu, direct float2 stores ----
    float2 b2[2];
    #pragma unroll
    for (int j = 0; j < 2; j++) {
        int ch = n0 + j * 8 + 2 * tr;
        b2[j] = make_float2(bias[deg * HID + ch], bias[deg * HID + ch + 1]);
    }
    #pragma unroll
    for (int m = 0; m < 2; m++) {
        int a0 = satom[mh * 32 + m * 16 + tq];
        int a1 = satom[mh * 32 + m * 16 + tq + 8];
        #pragma unroll
        for (int j = 0; j < 2; j++) {
            int ch = n0 + j * 8 + 2 * tr;
            if (a0 >= 0)
                *reinterpret_cast<float2*>(&g_x1[(size_t)a0 * HID + ch]) =
                    make_float2(fmaxf(acc4[m][j][0] + b2[j].x, 0.f),
                                fmaxf(acc4[m][j][1] + b2[j].y, 0.f));
            if (a1 >= 0)
                *reinterpret_cast<float2*>(&g_x1[(size_t)a1 * HID + ch]) =
                    make_float2(fmaxf(acc4[m][j][2] + b2[j].x, 0.f),
                                fmaxf(acc4[m][j][3] + b2[j].y, 0.f));
        }
    }
}

// ============================ pool ============================
__global__ __launch_bounds__(256)
void pool_kernel(const int* __restrict__ edges) {
    int w = threadIdx.x >> 5, lane = threadIdx.x & 31;
    int a = blockIdx.x * 8 + w;
    int rowbase = (a / NA) * NA;
    int e = (lane < DG) ? edges[a * DG + lane] : -1;
    unsigned ball = __ballot_sync(FULL, e >= 0);
    int nb[DG];
    #pragma unroll
    for (int d = 0; d < DG; d++) nb[d] = __shfl_sync(FULL, e, d);
    int o = lane * 4;
    float4 v = *reinterpret_cast<const float4*>(g_x1 + (size_t)a * HID + o);
    #pragma unroll
    for (int d = 0; d < DG; d++) {
        if (nb[d] >= 0) {
            float4 u = *reinterpret_cast<const float4*>(g_x1 + (size_t)(rowbase + nb[d]) * HID + o);
            v.x = fmaxf(v.x, u.x); v.y = fmaxf(v.y, u.y);
            v.z = fmaxf(v.z, u.z); v.w = fmaxf(v.w, u.w);
        }
    }
    if (ball == 0u) v = make_float4(0.f, 0.f, 0.f, 0.f);
    *reinterpret_cast<float4*>(g_x2 + (size_t)a * HID + o) = v;
}

// ============================ gout (mma.sync, 512 threads) ============================
__global__ __launch_bounds__(512, 2)
void gout_mma_kernel(const int*   __restrict__ edges,
                     const float* __restrict__ bonds,
                     const float* __restrict__ bo,
                     const float* __restrict__ Wfc,
                     const float* __restrict__ bfc,
                     float* __restrict__ out) {
    constexpr int KP2 = 72, NCH = 9, FS2 = 76;
    __shared__ __align__(16) uint32_t fh[64 * FS2];
    __shared__ __align__(16) uint32_t fl[64 * FS2];
    __shared__ float svalid[64];
    __shared__ float sred2[2][HID];

    int tid = threadIdx.x, w16 = tid >> 5, lane = tid & 31;
    int ng = w16 & 7, mh = w16 >> 3;
    int tq = lane >> 2, tr = lane & 3;
    int g = blockIdx.x;
    int rowbase = g * NA;

    // ---- edge prefetch: 24 edges (4 atom slots x 6) ----
    int e0 = -1;
    if (lane < 24) {
        int al0 = w16 * 4 + lane / 6;
        if (al0 < NA) e0 = edges[(rowbase + al0) * DG + lane % 6];
    }

    // ---- stage A: inline pool2 (float4) + bondsum + validity ----
    #pragma unroll
    for (int j = 0; j < 4; j++) {
        int al = w16 * 4 + j;
        bool ok = (al < NA);
        int a = rowbase + (ok ? al : 0);
        int nb[DG];
        #pragma unroll
        for (int d = 0; d < DG; d++) nb[d] = __shfl_sync(FULL, e0, j * 6 + d);
        bool anyn = (nb[0] >= 0) | (nb[1] >= 0) | (nb[2] >= 0) |
                    (nb[3] >= 0) | (nb[4] >= 0) | (nb[5] >= 0);
        bool valid = ok && anyn;

        float4 v = make_float4(0.f, 0.f, 0.f, 0.f);
        if (valid) {
            v = *reinterpret_cast<const float4*>(g_x1 + (size_t)a * HID + 4 * lane);
            #pragma unroll
            for (int d = 0; d < DG; d++)
                if (nb[d] >= 0) {
                    float4 u = *reinterpret_cast<const float4*>(
                        g_x1 + (size_t)(rowbase + nb[d]) * HID + 4 * lane);
                    v.x = fmaxf(v.x, u.x); v.y = fmaxf(v.y, u.y);
                    v.z = fmaxf(v.z, u.z); v.w = fmaxf(v.w, u.w);
                }
        }
        int kp0 = 2 * lane;
        *reinterpret_cast<uint2*>(&fh[al * FS2 + kp0]) =
            make_uint2(packbf(v.x, v.y), packbf(v.z, v.w));
        *reinterpret_cast<uint2*>(&fl[al * FS2 + kp0]) =
            make_uint2(packlo(v.x, v.y), packlo(v.z, v.w));
        if (lane < 8) {
            int kp = 64 + lane;
            float s0 = 0.f, s1 = 0.f;
            if (valid) {
                int f0 = 2 * lane, f1 = 2 * lane + 1;
                if (f0 < BF) {
                    const float* bp = bonds + (size_t)a * (DG * BF) + f0;
                    s0 = bp[0] + bp[6] + bp[12] + bp[18] + bp[24] + bp[30];
                }
                if (f1 < BF) {
                    const float* bp = bonds + (size_t)a * (DG * BF) + f1;
                    s1 = bp[0] + bp[6] + bp[12] + bp[18] + bp[24] + bp[30];
                }
            }
            fh[al * FS2 + kp] = packbf(s0, s1);
            fl[al * FS2 + kp] = packlo(s0, s1);
        }
        if (lane == 0) svalid[al] = valid ? 1.f : 0.f;
    }
    __syncthreads();

    // ---- GEMM: warp -> 16 ch x 32 atoms ----
    int n0 = ng * 16;
    float acc4[2][2][4];
    #pragma unroll
    for (int m = 0; m < 2; m++)
        #pragma unroll
        for (int j = 0; j < 2; j++)
            #pragma unroll
            for (int q = 0; q < 4; q++) acc4[m][j][q] = 0.f;

    const uint4* wb = g_WBo + ng * 64 + lane;

    uint32_t ah_base = smem_u32(fh) + 4 * ((mh * 32 + (lane & 15)) * FS2 + (lane >> 4) * 4);
    uint32_t al_base = smem_u32(fl) + 4 * ((mh * 32 + (lane & 15)) * FS2 + (lane >> 4) * 4);

    #pragma unroll
    for (int c = 0; c < NCH; c++) {
        uint32_t Ah[2][4], Al[2][4];
        #pragma unroll
        for (int m = 0; m < 2; m++) {
            uint32_t off = 4 * (m * 16 * FS2 + c * 8);
            LDSM_X4(Ah[m], ah_base + off);
            LDSM_X4(Al[m], al_base + off);
        }
        uint4 b0 = wb[c * 512];
        uint4 b1 = wb[c * 512 + 32];
        uint32_t Bh[2][2] = {{b0.x, b0.y}, {b1.x, b1.y}};
        uint32_t Bl[2][2] = {{b0.z, b0.w}, {b1.z, b1.w}};

        #pragma unroll
        for (int m = 0; m < 2; m++)
            #pragma unroll
            for (int j = 0; j < 2; j++) {
                mma16816(acc4[m][j], Ah[m], Bh[j]);
                mma16816(acc4[m][j], Al[m], Bh[j]);
                mma16816(acc4[m][j], Ah[m], Bl[j]);
            }
    }

    // ---- epilogue: bias + tanh + mask, reduce over this half's 32 atoms ----
    float2 b2[2];
    #pragma unroll
    for (int j = 0; j < 2; j++) {
        int ch = n0 + j * 8 + 2 * tr;
        b2[j] = make_float2(bo[ch], bo[ch + 1]);
    }
    float cs[2][2] = {{0.f, 0.f}, {0.f, 0.f}};
    #pragma unroll
    for (int m = 0; m < 2; m++) {
        float v0 = svalid[mh * 32 + m * 16 + tq];
        float v1 = svalid[mh * 32 + m * 16 + tq + 8];
        #pragma unroll
        for (int j = 0; j < 2; j++) {
            cs[j][0] += v0 * htanh(acc4[m][j][0] + b2[j].x)
                      + v1 * htanh(acc4[m][j][2] + b2[j].x);
            cs[j][1] += v0 * htanh(acc4[m][j][1] + b2[j].y)
                      + v1 * htanh(acc4[m][j][3] + b2[j].y);
        }
    }
    #pragma unroll
    for (int off = 4; off < 32; off <<= 1) {
        #pragma unroll
        for (int j = 0; j < 2; j++) {
            cs[j][0] += __shfl_xor_sync(FULL, cs[j][0], off);
            cs[j][1] += __shfl_xor_sync(FULL, cs[j][1], off);
        }
    }
    if (tq == 0) {
        #pragma unroll
        for (int j = 0; j < 2; j++) {
            int ch = n0 + j * 8 + 2 * tr;
            sred2[mh][ch]     = cs[j][0];
            sred2[mh][ch + 1] = cs[j][1];
        }
    }
    __syncthreads();

    if (tid < NC) {
        float v = bfc[tid];
        #pragma unroll 8
        for (int o = 0; o < HID; o++)
            v = fmaf(sred2[0][o] + sred2[1][o], Wfc[o * NC + tid], v);
        out[g * NC + tid] = 1.0f / (1.0f + expf(-v));
    }
}

// ---------------------------------------------------------------------------
extern "C" void kernel_launch(void* const* d_in, const int* in_sizes, int n_in,
                              void* d_out, int out_size) {
    const float* atoms = (const float*)d_in[0];
    const float* bonds = (const float*)d_in[1];
    const int*   edges = (const int*)  d_in[2];
    const float* W1    = (const float*)d_in[3];
    const float* b1    = (const float*)d_in[4];
    const float* W2    = (const float*)d_in[5];
    const float* b2    = (const float*)d_in[6];
    const float* Wo    = (const float*)d_in[7];
    const float* bo    = (const float*)d_in[8];
    const float* Wfc   = (const float*)d_in[9];
    const float* bfc   = (const float*)d_in[10];
    float* out = (float*)d_out;

    // launch order keeps conv1 as the 4th launch (the one ncu samples)
    zero_cnt_kernel<<<1, 32>>>();
    prep_kernel<<<BN / 256, 256>>>(edges);
    wprep_all_kernel<<<(6*3*512 + 6*9*512 + 9*512 + 255) / 256, 256>>>(W1, W2, Wo);

    conv_mma_kernel<AF, 48, 28, 0, true><<<MAXT, 512>>>(atoms, bonds, edges, b1);
    pool_kernel<<<BN / 8, 256>>>(edges);
    conv_mma_kernel<HID, 144, 76, 1, false><<<MAXT, 512>>>(nullptr, bonds, edges, b2);
    gout_mma_kernel<<<B, 512>>>(edges, bonds, bo, Wfc, bfc, out);
}